// round 14
// baseline (speedup 1.0000x reference)
#include <cuda_runtime.h>

#define BB 16
#define NN 4096
#define SS 1024
#define KS 32
#define NG (BB*SS)            /* 16384 groups */
#define MM (NG*KS)            /* 524288 samples */

// ---------------- scratch (device globals; no allocation) ----------------
__device__ float g_new_xyz[NG*3];
__device__ int   g_ball[NG*KS];
__device__ float g_h0[64*MM];
__device__ float g_h1[64*MM];
__device__ float g_h2[128*MM];
__device__ float g_e0[64*NG];     // extra-point activations
__device__ float g_e1[64*NG];
__device__ float g_e2[128*NG];
__device__ int   g_extra[NG];     // extra point index per group
__device__ int   g_uidx[NG];      // uncertain point index
__device__ int   g_umeta[NG];     // mode|us<<2|disp<<8|extraV<<9|allExcl<<10
__device__ float g_uw[NG];        // include-probability weight
__device__ float g_ab0[256];      // [mu|rs|gamma|beta] x64
__device__ float g_ab1[256];
__device__ float g_ab2[512];      // x128

// ---------------- helpers ----------------
__device__ __forceinline__ unsigned long long pk2(float a, float b) {
    unsigned long long r;
    asm("mov.b64 %0, {%1,%2};" : "=l"(r) : "f"(a), "f"(b));
    return r;
}
__device__ __forceinline__ void upk2(unsigned long long v, float& a, float& b) {
    asm("mov.b64 {%0,%1}, %2;" : "=f"(a), "=f"(b) : "l"(v));
}
__device__ __forceinline__ unsigned long long f2fma(unsigned long long a,
                                                    unsigned long long b,
                                                    unsigned long long c) {
    unsigned long long d;
    asm("fma.rn.f32x2 %0, %1, %2, %3;" : "=l"(d) : "l"(a), "l"(b), "l"(c));
    return d;
}
__device__ __forceinline__ float wredmax(float v) {
#pragma unroll
    for (int o = 16; o > 0; o >>= 1) v = fmaxf(v, __shfl_xor_sync(0xFFFFFFFFu, v, o));
    return v;
}

// ---------------- 1. farthest point sampling (bit-exact) ----------------
__global__ __launch_bounds__(512) void fps_kernel(const float* __restrict__ pc,
                                                  float* __restrict__ out) {
    const int b = blockIdx.x;
    const int tid = threadIdx.x;
    const float* px = pc + b * 3 * NN;
    const float* py = px + NN;
    const float* pz = px + 2 * NN;

    float lx[8], ly[8], lz[8], ld[8];
#pragma unroll
    for (int j = 0; j < 8; j++) {
        int p = tid + j * 512;
        lx[j] = px[p]; ly[j] = py[p]; lz[j] = pz[p];
        ld[j] = 1e10f;
    }
    __shared__ unsigned long long swk[16];
    __shared__ int sfar;

    int far = 0;
    for (int s = 0; s < SS; s++) {
        float cx = __ldg(px + far), cy = __ldg(py + far), cz = __ldg(pz + far);
        if (tid == 0) {
            out[b * 3 * SS + s]          = cx;
            out[b * 3 * SS + SS + s]     = cy;
            out[b * 3 * SS + 2 * SS + s] = cz;
            int bs = b * SS + s;
            g_new_xyz[bs * 3 + 0] = cx;
            g_new_xyz[bs * 3 + 1] = cy;
            g_new_xyz[bs * 3 + 2] = cz;
        }
        float ncx = -cx, ncy = -cy, ncz = -cz;
        float bd = 0.0f;
        int bi = tid;
#pragma unroll
        for (int j = 0; j < 8; j++) {
            float dx = __fadd_rn(lx[j], ncx);
            float dy = __fadd_rn(ly[j], ncy);
            float dz = __fadd_rn(lz[j], ncz);
            float d = __fadd_rn(__fadd_rn(__fmul_rn(dx, dx), __fmul_rn(dy, dy)),
                                __fmul_rn(dz, dz));
            float nd = fminf(ld[j], d);
            ld[j] = nd;
            if (nd > bd) { bd = nd; bi = tid + j * 512; }
        }
        unsigned long long key =
            ((unsigned long long)__float_as_uint(bd) << 32) |
            (unsigned long long)(0xFFFFFFFFu - (unsigned)bi);
#pragma unroll
        for (int off = 16; off > 0; off >>= 1) {
            unsigned long long o = __shfl_down_sync(0xFFFFFFFFu, key, off);
            if (o > key) key = o;
        }
        if ((tid & 31) == 0) swk[tid >> 5] = key;
        __syncthreads();
        if (tid < 32) {
            unsigned long long k = (tid < 16) ? swk[tid] : 0ull;
#pragma unroll
            for (int off = 8; off > 0; off >>= 1) {
                unsigned long long o = __shfl_down_sync(0xFFFFFFFFu, k, off);
                if (o > k) k = o;
            }
            if (tid == 0)
                sfar = (int)(0xFFFFFFFFu - (unsigned)(k & 0xFFFFFFFFull));
        }
        __syncthreads();
        far = sfar;
    }
}

// ------- 2. ball query with borderline-uncertainty tracking -------
__global__ __launch_bounds__(256) void ball_kernel(const float* __restrict__ pc) {
    const int gw = (blockIdx.x * 256 + threadIdx.x) >> 5;
    const int lane = threadIdx.x & 31;
    const int wslot = (threadIdx.x >> 5);
    const int b = gw >> 10;
    const float* px = pc + b * 3 * NN;
    const float* py = px + NN;
    const float* pz = px + 2 * NN;

    float sx = g_new_xyz[gw * 3 + 0];
    float sy = g_new_xyz[gw * 3 + 1];
    float sz = g_new_xyz[gw * 3 + 2];
    float ss = __fadd_rn(__fadd_rn(__fmul_rn(sx, sx), __fmul_rn(sy, sy)),
                         __fmul_rn(sz, sz));
    const float R2 = (float)(0.2 * 0.2);
    const double R2D = (double)R2;
    const double sxd = (double)sx, syd = (double)sy, szd = (double)sz;

    __shared__ int sidx[8][32];
    __shared__ int salt[8];
    int* my = sidx[wslot];
    if (lane == 0) salt[wslot] = -1;
    __syncwarp();

    // lane-local best uncertain candidate
    float aD = 1e30f;   // |signed delta|
    float aSD = 0.f;    // signed delta = R2D - dd  (>0 => truly inside)
    int aI = -1, aP = 0;

    int cnt = 0;
    for (int base = 0; base < NN; base += 32) {
        int i = base + lane;
        float x = px[i], y = py[i], z = pz[i];
        float pp = __fadd_rn(__fadd_rn(__fmul_rn(x, x), __fmul_rn(y, y)),
                             __fmul_rn(z, z));
        float dot = __fmaf_rn(sz, z, __fmaf_rn(sy, y, __fmul_rn(sx, x)));
        float d = __fadd_rn(__fadd_rn(__fmul_rn(-2.0f, dot), ss), pp);
        bool isLast = (i == NN - 1);
        bool valid;
        if (fabsf(d - R2) < 1e-4f) {
            double dx = sxd - (double)x;
            double dy = syd - (double)y;
            double dz = szd - (double)z;
            double dd = dx * dx + dy * dy + dz * dz;
            valid = (dd <= R2D);
            if (!isLast) {
                float sd = (float)(R2D - dd);
                float ad = fabsf(sd);
                if (ad < 1.2e-6f && ad < aD) {
                    aD = ad; aSD = sd; aI = i; aP = valid ? 1 : 0;
                }
            }
        } else {
            valid = !(d > R2);
        }
        valid = valid && !isLast;
        unsigned m = __ballot_sync(0xFFFFFFFFu, valid);
        int pos = cnt + __popc(m & ((1u << lane) - 1u));
        if (valid && pos < KS) my[pos] = i;
        if (valid && pos == KS) salt[wslot] = i;   // 33rd member
        cnt += __popc(m);
        if (cnt >= KS + 1) break;
    }
    __syncwarp();

    // warp-reduce uncertain candidate (min |delta|, tie -> min index)
#pragma unroll
    for (int off = 16; off > 0; off >>= 1) {
        float oD = __shfl_xor_sync(0xFFFFFFFFu, aD, off);
        float oSD = __shfl_xor_sync(0xFFFFFFFFu, aSD, off);
        int oI = __shfl_xor_sync(0xFFFFFFFFu, aI, off);
        int oP = __shfl_xor_sync(0xFFFFFFFFu, aP, off);
        if (oD < aD || (oD == aD && oI >= 0 && (aI < 0 || oI < aI))) {
            aD = oD; aSD = oSD; aI = oI; aP = oP;
        }
    }

    int c2 = cnt < KS ? cnt : KS;
    int vball;
    if (cnt == 0) vball = NN - 1;
    else vball = (lane < c2) ? my[lane] : my[0];
    g_ball[gw * KS + lane] = vball;

    // decide mode (uniform across warp)
    int mode = 0, us = 0, disp = 0, allExcl = 0, extraIdx = -1;
    float w = 0.5f;
    if (aI >= 0 && aD < 1.2e-6f) {
        w = fminf(fmaxf(0.5f + aSD * (1.0f / 8e-7f), 0.0f), 1.0f);
        if (aP) {
            bool mine = (lane < c2) && (my[lane] == aI);
            unsigned mm = __ballot_sync(0xFFFFFFFFu, mine);
            if (mm) {
                mode = 1;
                us = __ffs(mm) - 1;
                if (cnt == 1) extraIdx = NN - 1;     // B-set empty -> sentinel group
                else extraIdx = salt[wslot];         // may be -1
            }
        } else {
            bool relevant = (cnt < KS) || (aI < my[KS - 1]);
            if (relevant) {
                mode = 2;
                disp = (cnt >= KS) ? 1 : 0;
                allExcl = (cnt == 0) ? 1 : 0;
                extraIdx = aI;
            }
        }
    }
    if (lane == 0) {
        g_umeta[gw] = mode | (us << 2) | (disp << 8) |
                      ((extraIdx >= 0 ? 1 : 0) << 9) | (allExcl << 10);
        g_uw[gw] = w;
        g_uidx[gw] = aI;
        g_extra[gw] = (extraIdx >= 0) ? extraIdx : (NN - 1);
    }
}

// ---------------- 3. layer-0 GEMM (gather + concat fused) ----------------
__global__ __launch_bounds__(256) void gemm0_kernel(const float* __restrict__ pc,
                                                    const float* __restrict__ feat,
                                                    const float* __restrict__ W,
                                                    const float* __restrict__ bias) {
    const int bs = blockIdx.x;
    const int b = bs >> 10;
    const int tid = threadIdx.x;
    const int lane = tid & 31;
    const int w = tid >> 5;

    __shared__ __align__(16) float ws[67 * 64];
    __shared__ float xs[67 * 32];
    __shared__ int sidx[32];

    for (int i = tid; i < 67 * 64; i += 256) {
        int o = i / 67, c = i - o * 67;
        ws[c * 64 + o] = W[i];
    }
    if (tid < 32) sidx[tid] = g_ball[bs * 32 + tid];
    __syncthreads();

    const float* pb = pc + b * 3 * NN;
    const float* fb = feat + b * 64 * NN;
    for (int i = tid; i < 67 * 32; i += 256) {
        int c = i >> 5, l = i & 31;
        int p = sidx[l];
        float v;
        if (c < 3) v = __fsub_rn(pb[c * NN + p], g_new_xyz[bs * 3 + c]);
        else       v = fb[(c - 3) * NN + p];
        xs[i] = v;
    }
    __syncthreads();

    const int o0 = w * 8;
    unsigned long long a0 = 0ull, a1 = 0ull, a2 = 0ull, a3 = 0ull;
#pragma unroll 4
    for (int c = 0; c < 67; c++) {
        float xv = xs[c * 32 + lane];
        unsigned long long x2 = pk2(xv, xv);
        const ulonglong2* wp = reinterpret_cast<const ulonglong2*>(ws + c * 64 + o0);
        ulonglong2 wA = wp[0], wB = wp[1];
        a0 = f2fma(x2, wA.x, a0);
        a1 = f2fma(x2, wA.y, a1);
        a2 = f2fma(x2, wB.x, a2);
        a3 = f2fma(x2, wB.y, a3);
    }
    float h[8];
    upk2(a0, h[0], h[1]); upk2(a1, h[2], h[3]);
    upk2(a2, h[4], h[5]); upk2(a3, h[6], h[7]);
    const int mbase = bs * 32 + lane;
#pragma unroll
    for (int j = 0; j < 8; j++)
        g_h0[(o0 + j) * MM + mbase] = __fadd_rn(h[j], bias[o0 + j]);
}

// ---------------- 3x. layer-0 for extra points (32 groups per block) ----------------
__global__ __launch_bounds__(256) void gemm0x_kernel(const float* __restrict__ pc,
                                                     const float* __restrict__ feat,
                                                     const float* __restrict__ W,
                                                     const float* __restrict__ bias) {
    const int bs0 = blockIdx.x * 32;
    const int b = bs0 >> 10;
    const int tid = threadIdx.x;
    const int lane = tid & 31;
    const int w = tid >> 5;

    __shared__ __align__(16) float ws[67 * 64];
    __shared__ float xs[67 * 32];
    __shared__ int sidx[32];

    for (int i = tid; i < 67 * 64; i += 256) {
        int o = i / 67, c = i - o * 67;
        ws[c * 64 + o] = W[i];
    }
    if (tid < 32) sidx[tid] = g_extra[bs0 + tid];
    __syncthreads();

    const float* pb = pc + b * 3 * NN;
    const float* fb = feat + b * 64 * NN;
    for (int i = tid; i < 67 * 32; i += 256) {
        int c = i >> 5, l = i & 31;
        int p = sidx[l];
        float v;
        if (c < 3) v = __fsub_rn(pb[c * NN + p], g_new_xyz[(bs0 + l) * 3 + c]);
        else       v = fb[(c - 3) * NN + p];
        xs[i] = v;
    }
    __syncthreads();

    const int o0 = w * 8;
    unsigned long long a0 = 0ull, a1 = 0ull, a2 = 0ull, a3 = 0ull;
#pragma unroll 4
    for (int c = 0; c < 67; c++) {
        float xv = xs[c * 32 + lane];
        unsigned long long x2 = pk2(xv, xv);
        const ulonglong2* wp = reinterpret_cast<const ulonglong2*>(ws + c * 64 + o0);
        ulonglong2 wA = wp[0], wB = wp[1];
        a0 = f2fma(x2, wA.x, a0);
        a1 = f2fma(x2, wA.y, a1);
        a2 = f2fma(x2, wB.x, a2);
        a3 = f2fma(x2, wB.y, a3);
    }
    float h[8];
    upk2(a0, h[0], h[1]); upk2(a1, h[2], h[3]);
    upk2(a2, h[4], h[5]); upk2(a3, h[6], h[7]);
#pragma unroll
    for (int j = 0; j < 8; j++)
        g_e0[(o0 + j) * NG + bs0 + lane] = __fadd_rn(h[j], bias[o0 + j]);
}

// ---------------- 3b. mid/last GEMMs with fused bn+relu ----------------
template <int COUT, int LAYER>
__global__ __launch_bounds__(COUT * 4) void gemm_mid_kernel(
    const float* __restrict__ W, const float* __restrict__ bias) {
    const float* hin = (LAYER == 1) ? g_h0 : g_h1;
    const float* ab  = (LAYER == 1) ? g_ab0 : g_ab1;
    float* hout = (LAYER == 1) ? g_h1 : g_h2;

    const int bs = blockIdx.x;
    const int tid = threadIdx.x;
    const int lane = tid & 31;
    const int w = tid >> 5;
    const int NT = COUT * 4;

    __shared__ __align__(16) float ws[64 * COUT];
    __shared__ float xs[64 * 32];

    for (int i = tid; i < 64 * COUT; i += NT) {
        int o = i >> 6, c = i & 63;
        ws[c * COUT + o] = W[i];
    }
    for (int i = tid; i < 64 * 32; i += NT) {
        int c = i >> 5, l = i & 31;
        float v = hin[c * MM + bs * 32 + l];
        float t = __fmul_rn(__fmul_rn(__fsub_rn(v, ab[c]), ab[64 + c]), ab[128 + c]);
        t = fmaxf(__fadd_rn(t, ab[192 + c]), 0.0f);
        xs[i] = t;
    }
    __syncthreads();

    const int o0 = w * 8;
    unsigned long long a0 = 0ull, a1 = 0ull, a2 = 0ull, a3 = 0ull;
#pragma unroll 4
    for (int c = 0; c < 64; c++) {
        float xv = xs[c * 32 + lane];
        unsigned long long x2 = pk2(xv, xv);
        const ulonglong2* wp = reinterpret_cast<const ulonglong2*>(ws + c * COUT + o0);
        ulonglong2 wA = wp[0], wB = wp[1];
        a0 = f2fma(x2, wA.x, a0);
        a1 = f2fma(x2, wA.y, a1);
        a2 = f2fma(x2, wB.x, a2);
        a3 = f2fma(x2, wB.y, a3);
    }
    float h[8];
    upk2(a0, h[0], h[1]); upk2(a1, h[2], h[3]);
    upk2(a2, h[4], h[5]); upk2(a3, h[6], h[7]);
    const int mbase = bs * 32 + lane;
#pragma unroll
    for (int j = 0; j < 8; j++)
        hout[(o0 + j) * MM + mbase] = __fadd_rn(h[j], bias[o0 + j]);
}

// extra-point version (input/output stride NG)
template <int COUT, int LAYER>
__global__ __launch_bounds__(COUT * 4) void gemm_midx_kernel(
    const float* __restrict__ W, const float* __restrict__ bias) {
    const float* hin = (LAYER == 1) ? g_e0 : g_e1;
    const float* ab  = (LAYER == 1) ? g_ab0 : g_ab1;
    float* hout = (LAYER == 1) ? g_e1 : g_e2;

    const int bs0 = blockIdx.x * 32;
    const int tid = threadIdx.x;
    const int lane = tid & 31;
    const int w = tid >> 5;
    const int NT = COUT * 4;

    __shared__ __align__(16) float ws[64 * COUT];
    __shared__ float xs[64 * 32];

    for (int i = tid; i < 64 * COUT; i += NT) {
        int o = i >> 6, c = i & 63;
        ws[c * COUT + o] = W[i];
    }
    for (int i = tid; i < 64 * 32; i += NT) {
        int c = i >> 5, l = i & 31;
        float v = hin[c * NG + bs0 + l];
        float t = __fmul_rn(__fmul_rn(__fsub_rn(v, ab[c]), ab[64 + c]), ab[128 + c]);
        t = fmaxf(__fadd_rn(t, ab[192 + c]), 0.0f);
        xs[i] = t;
    }
    __syncthreads();

    const int o0 = w * 8;
    unsigned long long a0 = 0ull, a1 = 0ull, a2 = 0ull, a3 = 0ull;
#pragma unroll 4
    for (int c = 0; c < 64; c++) {
        float xv = xs[c * 32 + lane];
        unsigned long long x2 = pk2(xv, xv);
        const ulonglong2* wp = reinterpret_cast<const ulonglong2*>(ws + c * COUT + o0);
        ulonglong2 wA = wp[0], wB = wp[1];
        a0 = f2fma(x2, wA.x, a0);
        a1 = f2fma(x2, wA.y, a1);
        a2 = f2fma(x2, wB.x, a2);
        a3 = f2fma(x2, wB.y, a3);
    }
    float h[8];
    upk2(a0, h[0], h[1]); upk2(a1, h[2], h[3]);
    upk2(a2, h[4], h[5]); upk2(a3, h[6], h[7]);
#pragma unroll
    for (int j = 0; j < 8; j++)
        hout[(o0 + j) * NG + bs0 + lane] = __fadd_rn(h[j], bias[o0 + j]);
}

// ------- 4. batch stats: two-pass direct reads, Kahan + tree -------
template <int L>
__global__ __launch_bounds__(1024) void statsA_kernel() {
    const float* h = (L == 0) ? g_h0 : ((L == 1) ? g_h1 : g_h2);
    float* ab = (L == 0) ? g_ab0 : ((L == 1) ? g_ab1 : g_ab2);
    const int c = blockIdx.x;
    const float* p = h + c * MM;

    float s = 0.f, comp = 0.f;
    for (int i = threadIdx.x; i < MM; i += 1024) {
        float y = __fsub_rn(p[i], comp);
        float t = __fadd_rn(s, y);
        comp = __fsub_rn(__fsub_rn(t, s), y);
        s = t;
    }
    __shared__ float sh[1024];
    sh[threadIdx.x] = s;
    __syncthreads();
    for (int off = 512; off > 0; off >>= 1) {
        if (threadIdx.x < off) sh[threadIdx.x] += sh[threadIdx.x + off];
        __syncthreads();
    }
    if (threadIdx.x == 0) ab[c] = sh[0] / (float)MM;
}

template <int L>
__global__ __launch_bounds__(1024) void statsB_kernel(const float* __restrict__ gamma,
                                                      const float* __restrict__ beta) {
    const int C = (L == 2) ? 128 : 64;
    const float* h = (L == 0) ? g_h0 : ((L == 1) ? g_h1 : g_h2);
    float* ab = (L == 0) ? g_ab0 : ((L == 1) ? g_ab1 : g_ab2);
    const int c = blockIdx.x;
    const float* p = h + c * MM;
    const float mu = ab[c];

    float s = 0.f, comp = 0.f;
    for (int i = threadIdx.x; i < MM; i += 1024) {
        float dv = __fsub_rn(p[i], mu);
        float v = __fmul_rn(dv, dv);
        float y = __fsub_rn(v, comp);
        float t = __fadd_rn(s, y);
        comp = __fsub_rn(__fsub_rn(t, s), y);
        s = t;
    }
    __shared__ float sh[1024];
    sh[threadIdx.x] = s;
    __syncthreads();
    for (int off = 512; off > 0; off >>= 1) {
        if (threadIdx.x < off) sh[threadIdx.x] += sh[threadIdx.x + off];
        __syncthreads();
    }
    if (threadIdx.x == 0) {
        float var = sh[0] / (float)MM;
        ab[C + c] = 1.0f / sqrtf(var + 1e-5f);
        ab[2 * C + c] = gamma[c];
        ab[3 * C + c] = beta[c];
    }
}

// ---------------- 5. bn+relu + soft-blended max over K ----------------
__global__ __launch_bounds__(128) void final_kernel(float* __restrict__ out) {
    const int bs = blockIdx.x;
    const int b = bs >> 10, s = bs & 1023;
    const int lane = threadIdx.x & 31, w = threadIdx.x >> 5;
    float* fo = out + BB * 3 * SS + b * 128 * SS + s;
    const int mbase = bs * 32 + lane;

    const int meta = g_umeta[bs];
    const int mode = meta & 3;
    const int us = (meta >> 2) & 63;
    const int disp = (meta >> 8) & 1;
    const int extraV = (meta >> 9) & 1;
    const int allExcl = (meta >> 10) & 1;
    const float wU = g_uw[bs];
    const int uIdx = g_uidx[bs];
    const int pidx = g_ball[bs * 32 + lane];

    for (int o = w; o < 128; o += 4) {
        float raw = g_h2[o * MM + mbase];
        float t = __fmul_rn(__fmul_rn(__fsub_rn(raw, g_ab2[o]), g_ab2[128 + o]),
                            g_ab2[256 + o]);
        float v = fmaxf(__fadd_rn(t, g_ab2[384 + o]), 0.0f);

        float res;
        if (mode == 0) {
            res = wredmax(v);
        } else {
            float eraw = g_e2[o * NG + bs];
            float et = __fmul_rn(__fmul_rn(__fsub_rn(eraw, g_ab2[o]), g_ab2[128 + o]),
                                 g_ab2[256 + o]);
            float ve = fmaxf(__fadd_rn(et, g_ab2[384 + o]), 0.0f);
            float A, B;
            if (mode == 1) {
                // A = include u (current slots); B = slots minus u (+alt)
                A = wredmax(v);
                float vB = (pidx == uIdx) ? -1e30f : v;
                B = wredmax(vB);
                if (extraV) B = fmaxf(B, ve);
            } else {
                // mode 2: A = slots (+u, minus displaced slot31 / all); B = slots
                float vA = ((disp && lane == 31) || allExcl) ? -1e30f : v;
                A = fmaxf(wredmax(vA), ve);
                B = wredmax(v);
            }
            res = wU * A + (1.0f - wU) * B;
        }
        if (lane == 0) fo[o * SS] = res;
    }
}

// ---------------- launcher ----------------
extern "C" void kernel_launch(void* const* d_in, const int* in_sizes, int n_in,
                              void* d_out, int out_size) {
    const float* pc   = (const float*)d_in[0];
    const float* feat = (const float*)d_in[1];
    const float* W0 = (const float*)d_in[2];
    const float* b0 = (const float*)d_in[3];
    const float* g0 = (const float*)d_in[4];
    const float* e0 = (const float*)d_in[5];
    const float* W1 = (const float*)d_in[6];
    const float* b1 = (const float*)d_in[7];
    const float* g1 = (const float*)d_in[8];
    const float* e1 = (const float*)d_in[9];
    const float* W2 = (const float*)d_in[10];
    const float* b2 = (const float*)d_in[11];
    const float* g2 = (const float*)d_in[12];
    const float* e2 = (const float*)d_in[13];
    float* out = (float*)d_out;

    fps_kernel<<<BB, 512>>>(pc, out);
    ball_kernel<<<NG / 8, 256>>>(pc);
    gemm0_kernel<<<NG, 256>>>(pc, feat, W0, b0);
    gemm0x_kernel<<<NG / 32, 256>>>(pc, feat, W0, b0);
    statsA_kernel<0><<<64, 1024>>>();
    statsB_kernel<0><<<64, 1024>>>(g0, e0);
    gemm_mid_kernel<64, 1><<<NG, 256>>>(W1, b1);
    gemm_midx_kernel<64, 1><<<NG / 32, 256>>>(W1, b1);
    statsA_kernel<1><<<64, 1024>>>();
    statsB_kernel<1><<<64, 1024>>>(g1, e1);
    gemm_mid_kernel<128, 2><<<NG, 512>>>(W2, b2);
    gemm_midx_kernel<128, 2><<<NG / 32, 512>>>(W2, b2);
    statsA_kernel<2><<<128, 1024>>>();
    statsB_kernel<2><<<128, 1024>>>(g2, e2);
    final_kernel<<<NG, 128>>>(out);
}

// round 15
// speedup vs baseline: 1.3560x; 1.3560x over previous
#include <cuda_runtime.h>

#define BB 16
#define NN 4096
#define SS 1024
#define KS 32
#define NG (BB*SS)            /* 16384 groups */
#define MM (NG*KS)            /* 524288 samples */
#define NB0 (NG/2)            /* gemm0 blocks: 8192 */
#define NB1 (NG/4)            /* mid1 blocks: 4096 */
#define NB2 (NG/2)            /* mid2 blocks: 8192 */

// ---------------- scratch (device globals; no allocation) ----------------
__device__ float g_new_xyz[NG*3];
__device__ int   g_ball[NG*KS];
__device__ float g_h0[64*MM];
__device__ float g_h1[64*MM];
__device__ float g_h2[128*MM];
__device__ float g_e0[64*NG];
__device__ float g_e1[64*NG];
__device__ float g_e2[128*NG];
__device__ int   g_extra[NG];
__device__ int   g_uidx[NG];
__device__ int   g_umeta[NG];
__device__ float g_uw[NG];
__device__ float g_ab0[256];      // [mu|rs|gamma|beta] x64
__device__ float g_ab1[256];
__device__ float g_ab2[512];      // x128
__device__ float g_ps0[64*NB0],  g_pq0[64*NB0];
__device__ float g_ps1[64*NB1],  g_pq1[64*NB1];
__device__ float g_ps2[128*NB2], g_pq2[128*NB2];

// ---------------- helpers ----------------
__device__ __forceinline__ unsigned long long pk2(float a, float b) {
    unsigned long long r;
    asm("mov.b64 %0, {%1,%2};" : "=l"(r) : "f"(a), "f"(b));
    return r;
}
__device__ __forceinline__ void upk2(unsigned long long v, float& a, float& b) {
    asm("mov.b64 {%0,%1}, %2;" : "=f"(a), "=f"(b) : "l"(v));
}
__device__ __forceinline__ unsigned long long f2fma(unsigned long long a,
                                                    unsigned long long b,
                                                    unsigned long long c) {
    unsigned long long d;
    asm("fma.rn.f32x2 %0, %1, %2, %3;" : "=l"(d) : "l"(a), "l"(b), "l"(c));
    return d;
}
__device__ __forceinline__ float wredsum(float v) {
#pragma unroll
    for (int o = 16; o > 0; o >>= 1) v += __shfl_xor_sync(0xFFFFFFFFu, v, o);
    return v;
}
__device__ __forceinline__ float wredmax(float v) {
#pragma unroll
    for (int o = 16; o > 0; o >>= 1) v = fmaxf(v, __shfl_xor_sync(0xFFFFFFFFu, v, o));
    return v;
}

// ---------------- 1. farthest point sampling (bit-exact) ----------------
__global__ __launch_bounds__(1024) void fps_kernel(const float* __restrict__ pc,
                                                   float* __restrict__ out) {
    const int b = blockIdx.x;
    const int tid = threadIdx.x;
    const float* px = pc + b * 3 * NN;
    const float* py = px + NN;
    const float* pz = px + 2 * NN;

    float lx[4], ly[4], lz[4], ld[4];
#pragma unroll
    for (int j = 0; j < 4; j++) {
        int p = tid + j * 1024;
        lx[j] = px[p]; ly[j] = py[p]; lz[j] = pz[p];
        ld[j] = 1e10f;
    }
    __shared__ unsigned long long swk[32];
    __shared__ int sfar;

    int far = 0;
    for (int s = 0; s < SS; s++) {
        float cx = __ldg(px + far), cy = __ldg(py + far), cz = __ldg(pz + far);
        if (tid == 0) {
            out[b * 3 * SS + s]          = cx;
            out[b * 3 * SS + SS + s]     = cy;
            out[b * 3 * SS + 2 * SS + s] = cz;
            int bs = b * SS + s;
            g_new_xyz[bs * 3 + 0] = cx;
            g_new_xyz[bs * 3 + 1] = cy;
            g_new_xyz[bs * 3 + 2] = cz;
        }
        float ncx = -cx, ncy = -cy, ncz = -cz;
        float bd = 0.0f;
        int bi = tid;
#pragma unroll
        for (int j = 0; j < 4; j++) {
            float dx = __fadd_rn(lx[j], ncx);
            float dy = __fadd_rn(ly[j], ncy);
            float dz = __fadd_rn(lz[j], ncz);
            float d = __fadd_rn(__fadd_rn(__fmul_rn(dx, dx), __fmul_rn(dy, dy)),
                                __fmul_rn(dz, dz));
            float nd = fminf(ld[j], d);
            ld[j] = nd;
            if (nd > bd) { bd = nd; bi = tid + j * 1024; }
        }
        unsigned long long key =
            ((unsigned long long)__float_as_uint(bd) << 32) |
            (unsigned long long)(0xFFFFFFFFu - (unsigned)bi);
#pragma unroll
        for (int off = 16; off > 0; off >>= 1) {
            unsigned long long o = __shfl_down_sync(0xFFFFFFFFu, key, off);
            if (o > key) key = o;
        }
        if ((tid & 31) == 0) swk[tid >> 5] = key;
        __syncthreads();
        if (tid < 32) {
            unsigned long long k = swk[tid];
#pragma unroll
            for (int off = 16; off > 0; off >>= 1) {
                unsigned long long o = __shfl_down_sync(0xFFFFFFFFu, k, off);
                if (o > k) k = o;
            }
            if (tid == 0)
                sfar = (int)(0xFFFFFFFFu - (unsigned)(k & 0xFFFFFFFFull));
        }
        __syncthreads();
        far = sfar;
    }
}

// ------- 2. ball query with borderline-uncertainty tracking (FROZEN from R14) -------
__global__ __launch_bounds__(256) void ball_kernel(const float* __restrict__ pc) {
    const int gw = (blockIdx.x * 256 + threadIdx.x) >> 5;
    const int lane = threadIdx.x & 31;
    const int wslot = (threadIdx.x >> 5);
    const int b = gw >> 10;
    const float* px = pc + b * 3 * NN;
    const float* py = px + NN;
    const float* pz = px + 2 * NN;

    float sx = g_new_xyz[gw * 3 + 0];
    float sy = g_new_xyz[gw * 3 + 1];
    float sz = g_new_xyz[gw * 3 + 2];
    float ss = __fadd_rn(__fadd_rn(__fmul_rn(sx, sx), __fmul_rn(sy, sy)),
                         __fmul_rn(sz, sz));
    const float R2 = (float)(0.2 * 0.2);
    const double R2D = (double)R2;
    const double sxd = (double)sx, syd = (double)sy, szd = (double)sz;

    __shared__ int sidx[8][32];
    __shared__ int salt[8];
    int* my = sidx[wslot];
    if (lane == 0) salt[wslot] = -1;
    __syncwarp();

    float aD = 1e30f;
    float aSD = 0.f;
    int aI = -1, aP = 0;

    int cnt = 0;
    for (int base = 0; base < NN; base += 32) {
        int i = base + lane;
        float x = px[i], y = py[i], z = pz[i];
        float pp = __fadd_rn(__fadd_rn(__fmul_rn(x, x), __fmul_rn(y, y)),
                             __fmul_rn(z, z));
        float dot = __fmaf_rn(sz, z, __fmaf_rn(sy, y, __fmul_rn(sx, x)));
        float d = __fadd_rn(__fadd_rn(__fmul_rn(-2.0f, dot), ss), pp);
        bool isLast = (i == NN - 1);
        bool valid;
        if (fabsf(d - R2) < 1e-4f) {
            double dx = sxd - (double)x;
            double dy = syd - (double)y;
            double dz = szd - (double)z;
            double dd = dx * dx + dy * dy + dz * dz;
            valid = (dd <= R2D);
            if (!isLast) {
                float sd = (float)(R2D - dd);
                float ad = fabsf(sd);
                if (ad < 1.2e-6f && ad < aD) {
                    aD = ad; aSD = sd; aI = i; aP = valid ? 1 : 0;
                }
            }
        } else {
            valid = !(d > R2);
        }
        valid = valid && !isLast;
        unsigned m = __ballot_sync(0xFFFFFFFFu, valid);
        int pos = cnt + __popc(m & ((1u << lane) - 1u));
        if (valid && pos < KS) my[pos] = i;
        if (valid && pos == KS) salt[wslot] = i;
        cnt += __popc(m);
        if (cnt >= KS + 1) break;
    }
    __syncwarp();

#pragma unroll
    for (int off = 16; off > 0; off >>= 1) {
        float oD = __shfl_xor_sync(0xFFFFFFFFu, aD, off);
        float oSD = __shfl_xor_sync(0xFFFFFFFFu, aSD, off);
        int oI = __shfl_xor_sync(0xFFFFFFFFu, aI, off);
        int oP = __shfl_xor_sync(0xFFFFFFFFu, aP, off);
        if (oD < aD || (oD == aD && oI >= 0 && (aI < 0 || oI < aI))) {
            aD = oD; aSD = oSD; aI = oI; aP = oP;
        }
    }

    int c2 = cnt < KS ? cnt : KS;
    int vball;
    if (cnt == 0) vball = NN - 1;
    else vball = (lane < c2) ? my[lane] : my[0];
    g_ball[gw * KS + lane] = vball;

    int mode = 0, us = 0, disp = 0, allExcl = 0, extraIdx = -1;
    float w = 0.5f;
    if (aI >= 0 && aD < 1.2e-6f) {
        w = fminf(fmaxf(0.5f + aSD * (1.0f / 8e-7f), 0.0f), 1.0f);
        if (aP) {
            bool mine = (lane < c2) && (my[lane] == aI);
            unsigned mm = __ballot_sync(0xFFFFFFFFu, mine);
            if (mm) {
                mode = 1;
                us = __ffs(mm) - 1;
                if (cnt == 1) extraIdx = NN - 1;
                else extraIdx = salt[wslot];
            }
        } else {
            bool relevant = (cnt < KS) || (aI < my[KS - 1]);
            if (relevant) {
                mode = 2;
                disp = (cnt >= KS) ? 1 : 0;
                allExcl = (cnt == 0) ? 1 : 0;
                extraIdx = aI;
            }
        }
    }
    if (lane == 0) {
        g_umeta[gw] = mode | (us << 2) | (disp << 8) |
                      ((extraIdx >= 0 ? 1 : 0) << 9) | (allExcl << 10);
        g_uw[gw] = w;
        g_uidx[gw] = aI;
        g_extra[gw] = (extraIdx >= 0) ? extraIdx : (NN - 1);
    }
}

// ---------------- 3. layer-0 GEMM: 2 groups/block, 2-sample register tiling ----------------
__global__ __launch_bounds__(256) void gemm0_kernel(const float* __restrict__ pc,
                                                    const float* __restrict__ feat,
                                                    const float* __restrict__ W,
                                                    const float* __restrict__ bias) {
    const int bs0 = blockIdx.x * 2;
    const int b = bs0 >> 10;
    const int tid = threadIdx.x;
    const int lane = tid & 31;
    const int w = tid >> 5;

    __shared__ __align__(16) float ws[67 * 64];
    __shared__ float xs[67 * 64];
    __shared__ int sidx[64];

    for (int i = tid; i < 67 * 64; i += 256) {
        int o = i / 67, c = i - o * 67;
        ws[c * 64 + o] = W[i];
    }
    if (tid < 64) sidx[tid] = g_ball[bs0 * 32 + tid];
    __syncthreads();

    const float* pb = pc + b * 3 * NN;
    const float* fb = feat + b * 64 * NN;
    for (int i = tid; i < 67 * 64; i += 256) {
        int c = i >> 6, l = i & 63;
        int p = sidx[l];
        float v;
        if (c < 3) v = __fsub_rn(pb[c * NN + p], g_new_xyz[(bs0 + (l >> 5)) * 3 + c]);
        else       v = fb[(c - 3) * NN + p];
        xs[c * 64 + l] = v;
    }
    __syncthreads();

    const int o0 = w * 8;
    unsigned long long A[2][4];
#pragma unroll
    for (int g = 0; g < 2; g++)
#pragma unroll
        for (int j = 0; j < 4; j++) A[g][j] = 0ull;

#pragma unroll 4
    for (int c = 0; c < 67; c++) {
        const ulonglong2* wp = reinterpret_cast<const ulonglong2*>(ws + c * 64 + o0);
        ulonglong2 wA = wp[0], wB = wp[1];
        float xv0 = xs[c * 64 + lane];
        float xv1 = xs[c * 64 + 32 + lane];
        unsigned long long x20 = pk2(xv0, xv0);
        unsigned long long x21 = pk2(xv1, xv1);
        A[0][0] = f2fma(x20, wA.x, A[0][0]);
        A[0][1] = f2fma(x20, wA.y, A[0][1]);
        A[0][2] = f2fma(x20, wB.x, A[0][2]);
        A[0][3] = f2fma(x20, wB.y, A[0][3]);
        A[1][0] = f2fma(x21, wA.x, A[1][0]);
        A[1][1] = f2fma(x21, wA.y, A[1][1]);
        A[1][2] = f2fma(x21, wB.x, A[1][2]);
        A[1][3] = f2fma(x21, wB.y, A[1][3]);
    }

    float h[2][8];
#pragma unroll
    for (int g = 0; g < 2; g++) {
        upk2(A[g][0], h[g][0], h[g][1]); upk2(A[g][1], h[g][2], h[g][3]);
        upk2(A[g][2], h[g][4], h[g][5]); upk2(A[g][3], h[g][6], h[g][7]);
        const int m = (bs0 + g) * 32 + lane;
#pragma unroll
        for (int j = 0; j < 8; j++) {
            float hj = __fadd_rn(h[g][j], bias[o0 + j]);
            h[g][j] = hj;
            g_h0[(o0 + j) * MM + m] = hj;
        }
    }
#pragma unroll
    for (int j = 0; j < 8; j++) {
        float sv = wredsum(h[0][j] + h[1][j]);
        float sq = wredsum(h[0][j] * h[0][j] + h[1][j] * h[1][j]);
        if (lane == 0) {
            g_ps0[(o0 + j) * NB0 + blockIdx.x] = sv;
            g_pq0[(o0 + j) * NB0 + blockIdx.x] = sq;
        }
    }
}

// ---------------- 3x. layer-0 for extra points (unchanged) ----------------
__global__ __launch_bounds__(256) void gemm0x_kernel(const float* __restrict__ pc,
                                                     const float* __restrict__ feat,
                                                     const float* __restrict__ W,
                                                     const float* __restrict__ bias) {
    const int bs0 = blockIdx.x * 32;
    const int b = bs0 >> 10;
    const int tid = threadIdx.x;
    const int lane = tid & 31;
    const int w = tid >> 5;

    __shared__ __align__(16) float ws[67 * 64];
    __shared__ float xs[67 * 32];
    __shared__ int sidx[32];

    for (int i = tid; i < 67 * 64; i += 256) {
        int o = i / 67, c = i - o * 67;
        ws[c * 64 + o] = W[i];
    }
    if (tid < 32) sidx[tid] = g_extra[bs0 + tid];
    __syncthreads();

    const float* pb = pc + b * 3 * NN;
    const float* fb = feat + b * 64 * NN;
    for (int i = tid; i < 67 * 32; i += 256) {
        int c = i >> 5, l = i & 31;
        int p = sidx[l];
        float v;
        if (c < 3) v = __fsub_rn(pb[c * NN + p], g_new_xyz[(bs0 + l) * 3 + c]);
        else       v = fb[(c - 3) * NN + p];
        xs[i] = v;
    }
    __syncthreads();

    const int o0 = w * 8;
    unsigned long long a0 = 0ull, a1 = 0ull, a2 = 0ull, a3 = 0ull;
#pragma unroll 4
    for (int c = 0; c < 67; c++) {
        float xv = xs[c * 32 + lane];
        unsigned long long x2 = pk2(xv, xv);
        const ulonglong2* wp = reinterpret_cast<const ulonglong2*>(ws + c * 64 + o0);
        ulonglong2 wA = wp[0], wB = wp[1];
        a0 = f2fma(x2, wA.x, a0);
        a1 = f2fma(x2, wA.y, a1);
        a2 = f2fma(x2, wB.x, a2);
        a3 = f2fma(x2, wB.y, a3);
    }
    float h[8];
    upk2(a0, h[0], h[1]); upk2(a1, h[2], h[3]);
    upk2(a2, h[4], h[5]); upk2(a3, h[6], h[7]);
#pragma unroll
    for (int j = 0; j < 8; j++)
        g_e0[(o0 + j) * NG + bs0 + lane] = __fadd_rn(h[j], bias[o0 + j]);
}

// ---------------- 3b. mid layer1: 4 groups/block, 4-sample register tiling ----------------
__global__ __launch_bounds__(256) void gemm_mid1_kernel(const float* __restrict__ W,
                                                        const float* __restrict__ bias) {
    const int bs0 = blockIdx.x * 4;
    const int tid = threadIdx.x;
    const int lane = tid & 31;
    const int w = tid >> 5;

    __shared__ __align__(16) float ws[64 * 64];
    __shared__ float xs[64 * 128];

    for (int i = tid; i < 64 * 64; i += 256) {
        int o = i >> 6, c = i & 63;
        ws[c * 64 + o] = W[i];
    }
    const float* ab = g_ab0;
    for (int i = tid; i < 64 * 128; i += 256) {
        int c = i >> 7, l = i & 127;
        float v = g_h0[c * MM + bs0 * 32 + l];
        float t = __fmul_rn(__fmul_rn(__fsub_rn(v, ab[c]), ab[64 + c]), ab[128 + c]);
        t = fmaxf(__fadd_rn(t, ab[192 + c]), 0.0f);
        xs[c * 128 + l] = t;
    }
    __syncthreads();

    const int o0 = w * 8;
    unsigned long long A[4][4];
#pragma unroll
    for (int g = 0; g < 4; g++)
#pragma unroll
        for (int j = 0; j < 4; j++) A[g][j] = 0ull;

#pragma unroll 2
    for (int c = 0; c < 64; c++) {
        const ulonglong2* wp = reinterpret_cast<const ulonglong2*>(ws + c * 64 + o0);
        ulonglong2 wA = wp[0], wB = wp[1];
#pragma unroll
        for (int g = 0; g < 4; g++) {
            float xv = xs[c * 128 + g * 32 + lane];
            unsigned long long x2 = pk2(xv, xv);
            A[g][0] = f2fma(x2, wA.x, A[g][0]);
            A[g][1] = f2fma(x2, wA.y, A[g][1]);
            A[g][2] = f2fma(x2, wB.x, A[g][2]);
            A[g][3] = f2fma(x2, wB.y, A[g][3]);
        }
    }

    float h[4][8];
#pragma unroll
    for (int g = 0; g < 4; g++) {
        upk2(A[g][0], h[g][0], h[g][1]); upk2(A[g][1], h[g][2], h[g][3]);
        upk2(A[g][2], h[g][4], h[g][5]); upk2(A[g][3], h[g][6], h[g][7]);
        const int m = (bs0 + g) * 32 + lane;
#pragma unroll
        for (int j = 0; j < 8; j++) {
            float hj = __fadd_rn(h[g][j], bias[o0 + j]);
            h[g][j] = hj;
            g_h1[(o0 + j) * MM + m] = hj;
        }
    }
#pragma unroll
    for (int j = 0; j < 8; j++) {
        float sv = wredsum((h[0][j] + h[1][j]) + (h[2][j] + h[3][j]));
        float sq = wredsum((h[0][j] * h[0][j] + h[1][j] * h[1][j]) +
                           (h[2][j] * h[2][j] + h[3][j] * h[3][j]));
        if (lane == 0) {
            g_ps1[(o0 + j) * NB1 + blockIdx.x] = sv;
            g_pq1[(o0 + j) * NB1 + blockIdx.x] = sq;
        }
    }
}

// ---------------- 3c. mid layer2: 2 groups/block, 512 threads ----------------
__global__ __launch_bounds__(512) void gemm_mid2_kernel(const float* __restrict__ W,
                                                        const float* __restrict__ bias) {
    const int bs0 = blockIdx.x * 2;
    const int tid = threadIdx.x;
    const int lane = tid & 31;
    const int w = tid >> 5;

    __shared__ __align__(16) float ws[64 * 128];
    __shared__ float xs[64 * 64];

    for (int i = tid; i < 64 * 128; i += 512) {
        int o = i >> 6, c = i & 63;
        ws[c * 128 + o] = W[i];
    }
    const float* ab = g_ab1;
    for (int i = tid; i < 64 * 64; i += 512) {
        int c = i >> 6, l = i & 63;
        float v = g_h1[c * MM + bs0 * 32 + l];
        float t = __fmul_rn(__fmul_rn(__fsub_rn(v, ab[c]), ab[64 + c]), ab[128 + c]);
        t = fmaxf(__fadd_rn(t, ab[192 + c]), 0.0f);
        xs[c * 64 + l] = t;
    }
    __syncthreads();

    const int o0 = w * 8;
    unsigned long long A[2][4];
#pragma unroll
    for (int g = 0; g < 2; g++)
#pragma unroll
        for (int j = 0; j < 4; j++) A[g][j] = 0ull;

#pragma unroll 4
    for (int c = 0; c < 64; c++) {
        const ulonglong2* wp = reinterpret_cast<const ulonglong2*>(ws + c * 128 + o0);
        ulonglong2 wA = wp[0], wB = wp[1];
        float xv0 = xs[c * 64 + lane];
        float xv1 = xs[c * 64 + 32 + lane];
        unsigned long long x20 = pk2(xv0, xv0);
        unsigned long long x21 = pk2(xv1, xv1);
        A[0][0] = f2fma(x20, wA.x, A[0][0]);
        A[0][1] = f2fma(x20, wA.y, A[0][1]);
        A[0][2] = f2fma(x20, wB.x, A[0][2]);
        A[0][3] = f2fma(x20, wB.y, A[0][3]);
        A[1][0] = f2fma(x21, wA.x, A[1][0]);
        A[1][1] = f2fma(x21, wA.y, A[1][1]);
        A[1][2] = f2fma(x21, wB.x, A[1][2]);
        A[1][3] = f2fma(x21, wB.y, A[1][3]);
    }

    float h[2][8];
#pragma unroll
    for (int g = 0; g < 2; g++) {
        upk2(A[g][0], h[g][0], h[g][1]); upk2(A[g][1], h[g][2], h[g][3]);
        upk2(A[g][2], h[g][4], h[g][5]); upk2(A[g][3], h[g][6], h[g][7]);
        const int m = (bs0 + g) * 32 + lane;
#pragma unroll
        for (int j = 0; j < 8; j++) {
            float hj = __fadd_rn(h[g][j], bias[o0 + j]);
            h[g][j] = hj;
            g_h2[(o0 + j) * MM + m] = hj;
        }
    }
#pragma unroll
    for (int j = 0; j < 8; j++) {
        float sv = wredsum(h[0][j] + h[1][j]);
        float sq = wredsum(h[0][j] * h[0][j] + h[1][j] * h[1][j]);
        if (lane == 0) {
            g_ps2[(o0 + j) * NB2 + blockIdx.x] = sv;
            g_pq2[(o0 + j) * NB2 + blockIdx.x] = sq;
        }
    }
}

// extra-point mid layers (unchanged)
template <int COUT, int LAYER>
__global__ __launch_bounds__(COUT * 4) void gemm_midx_kernel(
    const float* __restrict__ W, const float* __restrict__ bias) {
    const float* hin = (LAYER == 1) ? g_e0 : g_e1;
    const float* ab  = (LAYER == 1) ? g_ab0 : g_ab1;
    float* hout = (LAYER == 1) ? g_e1 : g_e2;

    const int bs0 = blockIdx.x * 32;
    const int tid = threadIdx.x;
    const int lane = tid & 31;
    const int w = tid >> 5;
    const int NT = COUT * 4;

    __shared__ __align__(16) float ws[64 * COUT];
    __shared__ float xs[64 * 32];

    for (int i = tid; i < 64 * COUT; i += NT) {
        int o = i >> 6, c = i & 63;
        ws[c * COUT + o] = W[i];
    }
    for (int i = tid; i < 64 * 32; i += NT) {
        int c = i >> 5, l = i & 31;
        float v = hin[c * NG + bs0 + l];
        float t = __fmul_rn(__fmul_rn(__fsub_rn(v, ab[c]), ab[64 + c]), ab[128 + c]);
        t = fmaxf(__fadd_rn(t, ab[192 + c]), 0.0f);
        xs[i] = t;
    }
    __syncthreads();

    const int o0 = w * 8;
    unsigned long long a0 = 0ull, a1 = 0ull, a2 = 0ull, a3 = 0ull;
#pragma unroll 4
    for (int c = 0; c < 64; c++) {
        float xv = xs[c * 32 + lane];
        unsigned long long x2 = pk2(xv, xv);
        const ulonglong2* wp = reinterpret_cast<const ulonglong2*>(ws + c * COUT + o0);
        ulonglong2 wA = wp[0], wB = wp[1];
        a0 = f2fma(x2, wA.x, a0);
        a1 = f2fma(x2, wA.y, a1);
        a2 = f2fma(x2, wB.x, a2);
        a3 = f2fma(x2, wB.y, a3);
    }
    float h[8];
    upk2(a0, h[0], h[1]); upk2(a1, h[2], h[3]);
    upk2(a2, h[4], h[5]); upk2(a3, h[6], h[7]);
#pragma unroll
    for (int j = 0; j < 8; j++)
        hout[(o0 + j) * NG + bs0 + lane] = __fadd_rn(h[j], bias[o0 + j]);
}

// ------- 4. stats finalize from per-block partials (deterministic) -------
template <int L>
__global__ __launch_bounds__(256) void stats_fin_kernel(const float* __restrict__ gamma,
                                                        const float* __restrict__ beta) {
    const int C = (L == 2) ? 128 : 64;
    const int NBLK = (L == 0) ? NB0 : ((L == 1) ? NB1 : NB2);
    const float* ps = (L == 0) ? g_ps0 : ((L == 1) ? g_ps1 : g_ps2);
    const float* pq = (L == 0) ? g_pq0 : ((L == 1) ? g_pq1 : g_pq2);
    float* ab = (L == 0) ? g_ab0 : ((L == 1) ? g_ab1 : g_ab2);

    const int c = blockIdx.x;
    float s = 0.f, q = 0.f;
    for (int i = threadIdx.x; i < NBLK; i += 256) {
        s += ps[c * NBLK + i];
        q += pq[c * NBLK + i];
    }
    s = wredsum(s);
    q = wredsum(q);
    __shared__ float sh[16];
    int lane = threadIdx.x & 31, w = threadIdx.x >> 5;
    if (lane == 0) { sh[w] = s; sh[8 + w] = q; }
    __syncthreads();
    if (threadIdx.x == 0) {
        float ts = 0.f, tq = 0.f;
#pragma unroll
        for (int i = 0; i < 8; i++) { ts += sh[i]; tq += sh[8 + i]; }
        const float inv = 1.0f / (float)MM;
        float mu = ts * inv;
        float var = tq * inv - mu * mu;
        ab[c] = mu;
        ab[C + c] = 1.0f / sqrtf(var + 1e-5f);
        ab[2 * C + c] = gamma[c];
        ab[3 * C + c] = beta[c];
    }
}

// ---------------- 5. bn+relu + soft-blended max over K (FROZEN from R14) ----------------
__global__ __launch_bounds__(128) void final_kernel(float* __restrict__ out) {
    const int bs = blockIdx.x;
    const int b = bs >> 10, s = bs & 1023;
    const int lane = threadIdx.x & 31, w = threadIdx.x >> 5;
    float* fo = out + BB * 3 * SS + b * 128 * SS + s;
    const int mbase = bs * 32 + lane;

    const int meta = g_umeta[bs];
    const int mode = meta & 3;
    const int disp = (meta >> 8) & 1;
    const int extraV = (meta >> 9) & 1;
    const int allExcl = (meta >> 10) & 1;
    const float wU = g_uw[bs];
    const int uIdx = g_uidx[bs];
    const int pidx = g_ball[bs * 32 + lane];

    for (int o = w; o < 128; o += 4) {
        float raw = g_h2[o * MM + mbase];
        float t = __fmul_rn(__fmul_rn(__fsub_rn(raw, g_ab2[o]), g_ab2[128 + o]),
                            g_ab2[256 + o]);
        float v = fmaxf(__fadd_rn(t, g_ab2[384 + o]), 0.0f);

        float res;
        if (mode == 0) {
            res = wredmax(v);
        } else {
            float eraw = g_e2[o * NG + bs];
            float et = __fmul_rn(__fmul_rn(__fsub_rn(eraw, g_ab2[o]), g_ab2[128 + o]),
                                 g_ab2[256 + o]);
            float ve = fmaxf(__fadd_rn(et, g_ab2[384 + o]), 0.0f);
            float A, B;
            if (mode == 1) {
                A = wredmax(v);
                float vB = (pidx == uIdx) ? -1e30f : v;
                B = wredmax(vB);
                if (extraV) B = fmaxf(B, ve);
            } else {
                float vA = ((disp && lane == 31) || allExcl) ? -1e30f : v;
                A = fmaxf(wredmax(vA), ve);
                B = wredmax(v);
            }
            res = wU * A + (1.0f - wU) * B;
        }
        if (lane == 0) fo[o * SS] = res;
    }
}

// ---------------- launcher ----------------
extern "C" void kernel_launch(void* const* d_in, const int* in_sizes, int n_in,
                              void* d_out, int out_size) {
    const float* pc   = (const float*)d_in[0];
    const float* feat = (const float*)d_in[1];
    const float* W0 = (const float*)d_in[2];
    const float* b0 = (const float*)d_in[3];
    const float* g0 = (const float*)d_in[4];
    const float* e0 = (const float*)d_in[5];
    const float* W1 = (const float*)d_in[6];
    const float* b1 = (const float*)d_in[7];
    const float* g1 = (const float*)d_in[8];
    const float* e1 = (const float*)d_in[9];
    const float* W2 = (const float*)d_in[10];
    const float* b2 = (const float*)d_in[11];
    const float* g2 = (const float*)d_in[12];
    const float* e2 = (const float*)d_in[13];
    float* out = (float*)d_out;

    fps_kernel<<<BB, 1024>>>(pc, out);
    ball_kernel<<<NG / 8, 256>>>(pc);
    gemm0_kernel<<<NB0, 256>>>(pc, feat, W0, b0);
    gemm0x_kernel<<<NG / 32, 256>>>(pc, feat, W0, b0);
    stats_fin_kernel<0><<<64, 256>>>(g0, e0);
    gemm_mid1_kernel<<<NB1, 256>>>(W1, b1);
    gemm_midx_kernel<64, 1><<<NG / 32, 256>>>(W1, b1);
    stats_fin_kernel<1><<<64, 256>>>(g1, e1);
    gemm_mid2_kernel<<<NB2, 512>>>(W2, b2);
    gemm_midx_kernel<128, 2><<<NG / 32, 512>>>(W2, b2);
    stats_fin_kernel<2><<<128, 256>>>(g2, e2);
    final_kernel<<<NG, 128>>>(out);
}

// round 16
// speedup vs baseline: 1.4872x; 1.0967x over previous
#include <cuda_runtime.h>

#define BB 16
#define NN 4096
#define SS 1024
#define KS 32
#define NG (BB*SS)            /* 16384 groups */
#define MM (NG*KS)            /* 524288 samples */
#define NB0 (NG/4)            /* 4096 */
#define NB1 (NG/4)            /* 4096 */
#define NB2 (NG/4)            /* 4096 */

// ---------------- scratch (device globals; no allocation) ----------------
__device__ float g_new_xyz[NG*3];
__device__ int   g_ball[NG*KS];
__device__ float g_h0[64*MM];
__device__ float g_h1[64*MM];
__device__ float g_h2[128*MM];
__device__ float g_e0[64*NG];
__device__ float g_e1[64*NG];
__device__ float g_e2[128*NG];
__device__ int   g_extra[NG];
__device__ int   g_uidx[NG];
__device__ int   g_umeta[NG];
__device__ float g_uw[NG];
__device__ float g_ab0[256];
__device__ float g_ab1[256];
__device__ float g_ab2[512];
__device__ float g_ps0[64*NB0],  g_pq0[64*NB0];
__device__ float g_ps1[64*NB1],  g_pq1[64*NB1];
__device__ float g_ps2[128*NB2], g_pq2[128*NB2];

// ---------------- helpers ----------------
__device__ __forceinline__ unsigned long long pk2(float a, float b) {
    unsigned long long r;
    asm("mov.b64 %0, {%1,%2};" : "=l"(r) : "f"(a), "f"(b));
    return r;
}
__device__ __forceinline__ void upk2(unsigned long long v, float& a, float& b) {
    asm("mov.b64 {%0,%1}, %2;" : "=f"(a), "=f"(b) : "l"(v));
}
__device__ __forceinline__ unsigned long long f2fma(unsigned long long a,
                                                    unsigned long long b,
                                                    unsigned long long c) {
    unsigned long long d;
    asm("fma.rn.f32x2 %0, %1, %2, %3;" : "=l"(d) : "l"(a), "l"(b), "l"(c));
    return d;
}
__device__ __forceinline__ float wredsum(float v) {
#pragma unroll
    for (int o = 16; o > 0; o >>= 1) v += __shfl_xor_sync(0xFFFFFFFFu, v, o);
    return v;
}
__device__ __forceinline__ float wredmax(float v) {
#pragma unroll
    for (int o = 16; o > 0; o >>= 1) v = fmaxf(v, __shfl_xor_sync(0xFFFFFFFFu, v, o));
    return v;
}

// ---------------- 1. farthest point sampling (bit-exact, FROZEN) ----------------
__global__ __launch_bounds__(1024) void fps_kernel(const float* __restrict__ pc,
                                                   float* __restrict__ out) {
    const int b = blockIdx.x;
    const int tid = threadIdx.x;
    const float* px = pc + b * 3 * NN;
    const float* py = px + NN;
    const float* pz = px + 2 * NN;

    float lx[4], ly[4], lz[4], ld[4];
#pragma unroll
    for (int j = 0; j < 4; j++) {
        int p = tid + j * 1024;
        lx[j] = px[p]; ly[j] = py[p]; lz[j] = pz[p];
        ld[j] = 1e10f;
    }
    __shared__ unsigned long long swk[32];
    __shared__ int sfar;

    int far = 0;
    for (int s = 0; s < SS; s++) {
        float cx = __ldg(px + far), cy = __ldg(py + far), cz = __ldg(pz + far);
        if (tid == 0) {
            out[b * 3 * SS + s]          = cx;
            out[b * 3 * SS + SS + s]     = cy;
            out[b * 3 * SS + 2 * SS + s] = cz;
            int bs = b * SS + s;
            g_new_xyz[bs * 3 + 0] = cx;
            g_new_xyz[bs * 3 + 1] = cy;
            g_new_xyz[bs * 3 + 2] = cz;
        }
        float ncx = -cx, ncy = -cy, ncz = -cz;
        float bd = 0.0f;
        int bi = tid;
#pragma unroll
        for (int j = 0; j < 4; j++) {
            float dx = __fadd_rn(lx[j], ncx);
            float dy = __fadd_rn(ly[j], ncy);
            float dz = __fadd_rn(lz[j], ncz);
            float d = __fadd_rn(__fadd_rn(__fmul_rn(dx, dx), __fmul_rn(dy, dy)),
                                __fmul_rn(dz, dz));
            float nd = fminf(ld[j], d);
            ld[j] = nd;
            if (nd > bd) { bd = nd; bi = tid + j * 1024; }
        }
        unsigned long long key =
            ((unsigned long long)__float_as_uint(bd) << 32) |
            (unsigned long long)(0xFFFFFFFFu - (unsigned)bi);
#pragma unroll
        for (int off = 16; off > 0; off >>= 1) {
            unsigned long long o = __shfl_down_sync(0xFFFFFFFFu, key, off);
            if (o > key) key = o;
        }
        if ((tid & 31) == 0) swk[tid >> 5] = key;
        __syncthreads();
        if (tid < 32) {
            unsigned long long k = swk[tid];
#pragma unroll
            for (int off = 16; off > 0; off >>= 1) {
                unsigned long long o = __shfl_down_sync(0xFFFFFFFFu, k, off);
                if (o > k) k = o;
            }
            if (tid == 0)
                sfar = (int)(0xFFFFFFFFu - (unsigned)(k & 0xFFFFFFFFull));
        }
        __syncthreads();
        far = sfar;
    }
}

// ------- 2. ball query with borderline-uncertainty tracking (FROZEN) -------
__global__ __launch_bounds__(256) void ball_kernel(const float* __restrict__ pc) {
    const int gw = (blockIdx.x * 256 + threadIdx.x) >> 5;
    const int lane = threadIdx.x & 31;
    const int wslot = (threadIdx.x >> 5);
    const int b = gw >> 10;
    const float* px = pc + b * 3 * NN;
    const float* py = px + NN;
    const float* pz = px + 2 * NN;

    float sx = g_new_xyz[gw * 3 + 0];
    float sy = g_new_xyz[gw * 3 + 1];
    float sz = g_new_xyz[gw * 3 + 2];
    float ss = __fadd_rn(__fadd_rn(__fmul_rn(sx, sx), __fmul_rn(sy, sy)),
                         __fmul_rn(sz, sz));
    const float R2 = (float)(0.2 * 0.2);
    const double R2D = (double)R2;
    const double sxd = (double)sx, syd = (double)sy, szd = (double)sz;

    __shared__ int sidx[8][32];
    __shared__ int salt[8];
    int* my = sidx[wslot];
    if (lane == 0) salt[wslot] = -1;
    __syncwarp();

    float aD = 1e30f;
    float aSD = 0.f;
    int aI = -1, aP = 0;

    int cnt = 0;
    for (int base = 0; base < NN; base += 32) {
        int i = base + lane;
        float x = px[i], y = py[i], z = pz[i];
        float pp = __fadd_rn(__fadd_rn(__fmul_rn(x, x), __fmul_rn(y, y)),
                             __fmul_rn(z, z));
        float dot = __fmaf_rn(sz, z, __fmaf_rn(sy, y, __fmul_rn(sx, x)));
        float d = __fadd_rn(__fadd_rn(__fmul_rn(-2.0f, dot), ss), pp);
        bool isLast = (i == NN - 1);
        bool valid;
        if (fabsf(d - R2) < 1e-4f) {
            double dx = sxd - (double)x;
            double dy = syd - (double)y;
            double dz = szd - (double)z;
            double dd = dx * dx + dy * dy + dz * dz;
            valid = (dd <= R2D);
            if (!isLast) {
                float sd = (float)(R2D - dd);
                float ad = fabsf(sd);
                if (ad < 1.2e-6f && ad < aD) {
                    aD = ad; aSD = sd; aI = i; aP = valid ? 1 : 0;
                }
            }
        } else {
            valid = !(d > R2);
        }
        valid = valid && !isLast;
        unsigned m = __ballot_sync(0xFFFFFFFFu, valid);
        int pos = cnt + __popc(m & ((1u << lane) - 1u));
        if (valid && pos < KS) my[pos] = i;
        if (valid && pos == KS) salt[wslot] = i;
        cnt += __popc(m);
        if (cnt >= KS + 1) break;
    }
    __syncwarp();

#pragma unroll
    for (int off = 16; off > 0; off >>= 1) {
        float oD = __shfl_xor_sync(0xFFFFFFFFu, aD, off);
        float oSD = __shfl_xor_sync(0xFFFFFFFFu, aSD, off);
        int oI = __shfl_xor_sync(0xFFFFFFFFu, aI, off);
        int oP = __shfl_xor_sync(0xFFFFFFFFu, aP, off);
        if (oD < aD || (oD == aD && oI >= 0 && (aI < 0 || oI < aI))) {
            aD = oD; aSD = oSD; aI = oI; aP = oP;
        }
    }

    int c2 = cnt < KS ? cnt : KS;
    int vball;
    if (cnt == 0) vball = NN - 1;
    else vball = (lane < c2) ? my[lane] : my[0];
    g_ball[gw * KS + lane] = vball;

    int mode = 0, us = 0, disp = 0, allExcl = 0, extraIdx = -1;
    float w = 0.5f;
    if (aI >= 0 && aD < 1.2e-6f) {
        w = fminf(fmaxf(0.5f + aSD * (1.0f / 8e-7f), 0.0f), 1.0f);
        if (aP) {
            bool mine = (lane < c2) && (my[lane] == aI);
            unsigned mm = __ballot_sync(0xFFFFFFFFu, mine);
            if (mm) {
                mode = 1;
                us = __ffs(mm) - 1;
                if (cnt == 1) extraIdx = NN - 1;
                else extraIdx = salt[wslot];
            }
        } else {
            bool relevant = (cnt < KS) || (aI < my[KS - 1]);
            if (relevant) {
                mode = 2;
                disp = (cnt >= KS) ? 1 : 0;
                allExcl = (cnt == 0) ? 1 : 0;
                extraIdx = aI;
            }
        }
    }
    if (lane == 0) {
        g_umeta[gw] = mode | (us << 2) | (disp << 8) |
                      ((extraIdx >= 0 ? 1 : 0) << 9) | (allExcl << 10);
        g_uw[gw] = w;
        g_uidx[gw] = aI;
        g_extra[gw] = (extraIdx >= 0) ? extraIdx : (NN - 1);
    }
}

// ---------------- 3x. layer-0 for extra points (unchanged, launched 3rd) ----------------
__global__ __launch_bounds__(256) void gemm0x_kernel(const float* __restrict__ pc,
                                                     const float* __restrict__ feat,
                                                     const float* __restrict__ W,
                                                     const float* __restrict__ bias) {
    const int bs0 = blockIdx.x * 32;
    const int b = bs0 >> 10;
    const int tid = threadIdx.x;
    const int lane = tid & 31;
    const int w = tid >> 5;

    __shared__ __align__(16) float ws[67 * 64];
    __shared__ float xs[67 * 32];
    __shared__ int sidx[32];

    for (int i = tid; i < 67 * 64; i += 256) {
        int o = i / 67, c = i - o * 67;
        ws[c * 64 + o] = W[i];
    }
    if (tid < 32) sidx[tid] = g_extra[bs0 + tid];
    __syncthreads();

    const float* pb = pc + b * 3 * NN;
    const float* fb = feat + b * 64 * NN;
    for (int i = tid; i < 67 * 32; i += 256) {
        int c = i >> 5, l = i & 31;
        int p = sidx[l];
        float v;
        if (c < 3) v = __fsub_rn(pb[c * NN + p], g_new_xyz[(bs0 + l) * 3 + c]);
        else       v = fb[(c - 3) * NN + p];
        xs[i] = v;
    }
    __syncthreads();

    const int o0 = w * 8;
    unsigned long long a0 = 0ull, a1 = 0ull, a2 = 0ull, a3 = 0ull;
#pragma unroll 4
    for (int c = 0; c < 67; c++) {
        float xv = xs[c * 32 + lane];
        unsigned long long x2 = pk2(xv, xv);
        const ulonglong2* wp = reinterpret_cast<const ulonglong2*>(ws + c * 64 + o0);
        ulonglong2 wA = wp[0], wB = wp[1];
        a0 = f2fma(x2, wA.x, a0);
        a1 = f2fma(x2, wA.y, a1);
        a2 = f2fma(x2, wB.x, a2);
        a3 = f2fma(x2, wB.y, a3);
    }
    float h[8];
    upk2(a0, h[0], h[1]); upk2(a1, h[2], h[3]);
    upk2(a2, h[4], h[5]); upk2(a3, h[6], h[7]);
#pragma unroll
    for (int j = 0; j < 8; j++)
        g_e0[(o0 + j) * NG + bs0 + lane] = __fadd_rn(h[j], bias[o0 + j]);
}

// ---------------- 3. layer-0 GEMM: 4 groups/block, float4 xs, dynamic smem ----------------
__global__ __launch_bounds__(256) void gemm0_kernel(const float* __restrict__ pc,
                                                    const float* __restrict__ feat,
                                                    const float* __restrict__ W,
                                                    const float* __restrict__ bias) {
    extern __shared__ __align__(16) float smem0[];
    float* ws = smem0;                 // 67*64
    float* xs = smem0 + 67 * 64;       // 67*128
    __shared__ int sidx[128];

    const int bs0 = blockIdx.x * 4;
    const int b = bs0 >> 10;
    const int tid = threadIdx.x;
    const int lane = tid & 31;
    const int w = tid >> 5;

    for (int i = tid; i < 67 * 64; i += 256) {
        int o = i / 67, c = i - o * 67;
        ws[c * 64 + o] = W[i];
    }
    if (tid < 128) sidx[tid] = g_ball[bs0 * 32 + tid];
    __syncthreads();

    const float* pb = pc + b * 3 * NN;
    const float* fb = feat + b * 64 * NN;
    for (int i = tid; i < 67 * 128; i += 256) {
        int c = i >> 7, s = i & 127;
        int p = sidx[s];
        float v;
        if (c < 3) v = __fsub_rn(pb[c * NN + p], g_new_xyz[(bs0 + (s >> 5)) * 3 + c]);
        else       v = fb[(c - 3) * NN + p];
        xs[c * 128 + s] = v;
    }
    __syncthreads();

    const int o0 = w * 8;
    unsigned long long A[4][4];
#pragma unroll
    for (int g = 0; g < 4; g++)
#pragma unroll
        for (int j = 0; j < 4; j++) A[g][j] = 0ull;

#pragma unroll 4
    for (int c = 0; c < 67; c++) {
        float4 xv = *reinterpret_cast<const float4*>(xs + c * 128 + lane * 4);
        const ulonglong2* wp = reinterpret_cast<const ulonglong2*>(ws + c * 64 + o0);
        ulonglong2 wA = wp[0], wB = wp[1];
        float xg[4] = {xv.x, xv.y, xv.z, xv.w};
#pragma unroll
        for (int g = 0; g < 4; g++) {
            unsigned long long x2 = pk2(xg[g], xg[g]);
            A[g][0] = f2fma(x2, wA.x, A[g][0]);
            A[g][1] = f2fma(x2, wA.y, A[g][1]);
            A[g][2] = f2fma(x2, wB.x, A[g][2]);
            A[g][3] = f2fma(x2, wB.y, A[g][3]);
        }
    }

    float h[4][8];
#pragma unroll
    for (int g = 0; g < 4; g++) {
        upk2(A[g][0], h[g][0], h[g][1]); upk2(A[g][1], h[g][2], h[g][3]);
        upk2(A[g][2], h[g][4], h[g][5]); upk2(A[g][3], h[g][6], h[g][7]);
    }
    const int base = bs0 * 32 + lane * 4;
#pragma unroll
    for (int j = 0; j < 8; j++) {
        float b4 = bias[o0 + j];
        float4 hv;
        hv.x = __fadd_rn(h[0][j], b4);
        hv.y = __fadd_rn(h[1][j], b4);
        hv.z = __fadd_rn(h[2][j], b4);
        hv.w = __fadd_rn(h[3][j], b4);
        *reinterpret_cast<float4*>(&g_h0[(o0 + j) * MM + base]) = hv;
        float sv = wredsum((hv.x + hv.y) + (hv.z + hv.w));
        float sq = wredsum((hv.x * hv.x + hv.y * hv.y) + (hv.z * hv.z + hv.w * hv.w));
        if (lane == 0) {
            g_ps0[(o0 + j) * NB0 + blockIdx.x] = sv;
            g_pq0[(o0 + j) * NB0 + blockIdx.x] = sq;
        }
    }
}

// ---------------- 3b. mid layer1: 4 groups/block, float4 xs (static 48KB) ----------------
__global__ __launch_bounds__(256) void gemm_mid1_kernel(const float* __restrict__ W,
                                                        const float* __restrict__ bias) {
    __shared__ __align__(16) float ws[64 * 64];
    __shared__ __align__(16) float xs[64 * 128];

    const int bs0 = blockIdx.x * 4;
    const int tid = threadIdx.x;
    const int lane = tid & 31;
    const int w = tid >> 5;

    for (int i = tid; i < 64 * 64; i += 256) {
        int o = i >> 6, c = i & 63;
        ws[c * 64 + o] = W[i];
    }
    const float* ab = g_ab0;
    for (int i = tid; i < 64 * 128; i += 256) {
        int c = i >> 7, l = i & 127;
        float v = g_h0[c * MM + bs0 * 32 + l];
        float t = __fmul_rn(__fmul_rn(__fsub_rn(v, ab[c]), ab[64 + c]), ab[128 + c]);
        t = fmaxf(__fadd_rn(t, ab[192 + c]), 0.0f);
        xs[c * 128 + l] = t;
    }
    __syncthreads();

    const int o0 = w * 8;
    unsigned long long A[4][4];
#pragma unroll
    for (int g = 0; g < 4; g++)
#pragma unroll
        for (int j = 0; j < 4; j++) A[g][j] = 0ull;

#pragma unroll 4
    for (int c = 0; c < 64; c++) {
        float4 xv = *reinterpret_cast<const float4*>(xs + c * 128 + lane * 4);
        const ulonglong2* wp = reinterpret_cast<const ulonglong2*>(ws + c * 64 + o0);
        ulonglong2 wA = wp[0], wB = wp[1];
        float xg[4] = {xv.x, xv.y, xv.z, xv.w};
#pragma unroll
        for (int g = 0; g < 4; g++) {
            unsigned long long x2 = pk2(xg[g], xg[g]);
            A[g][0] = f2fma(x2, wA.x, A[g][0]);
            A[g][1] = f2fma(x2, wA.y, A[g][1]);
            A[g][2] = f2fma(x2, wB.x, A[g][2]);
            A[g][3] = f2fma(x2, wB.y, A[g][3]);
        }
    }

    float h[4][8];
#pragma unroll
    for (int g = 0; g < 4; g++) {
        upk2(A[g][0], h[g][0], h[g][1]); upk2(A[g][1], h[g][2], h[g][3]);
        upk2(A[g][2], h[g][4], h[g][5]); upk2(A[g][3], h[g][6], h[g][7]);
    }
    const int base = bs0 * 32 + lane * 4;
#pragma unroll
    for (int j = 0; j < 8; j++) {
        float b4 = bias[o0 + j];
        float4 hv;
        hv.x = __fadd_rn(h[0][j], b4);
        hv.y = __fadd_rn(h[1][j], b4);
        hv.z = __fadd_rn(h[2][j], b4);
        hv.w = __fadd_rn(h[3][j], b4);
        *reinterpret_cast<float4*>(&g_h1[(o0 + j) * MM + base]) = hv;
        float sv = wredsum((hv.x + hv.y) + (hv.z + hv.w));
        float sq = wredsum((hv.x * hv.x + hv.y * hv.y) + (hv.z * hv.z + hv.w * hv.w));
        if (lane == 0) {
            g_ps1[(o0 + j) * NB1 + blockIdx.x] = sv;
            g_pq1[(o0 + j) * NB1 + blockIdx.x] = sq;
        }
    }
}

// ---------------- 3c. mid layer2: 4 groups/block, 512 threads, dynamic 64KB ----------------
__global__ __launch_bounds__(512) void gemm_mid2_kernel(const float* __restrict__ W,
                                                        const float* __restrict__ bias) {
    extern __shared__ __align__(16) float smem2[];
    float* ws = smem2;                 // 64*128
    float* xs = smem2 + 64 * 128;      // 64*128

    const int bs0 = blockIdx.x * 4;
    const int tid = threadIdx.x;
    const int lane = tid & 31;
    const int w = tid >> 5;

    for (int i = tid; i < 64 * 128; i += 512) {
        int o = i >> 6, c = i & 63;
        ws[c * 128 + o] = W[i];
    }
    const float* ab = g_ab1;
    for (int i = tid; i < 64 * 128; i += 512) {
        int c = i >> 7, l = i & 127;
        float v = g_h1[c * MM + bs0 * 32 + l];
        float t = __fmul_rn(__fmul_rn(__fsub_rn(v, ab[c]), ab[64 + c]), ab[128 + c]);
        t = fmaxf(__fadd_rn(t, ab[192 + c]), 0.0f);
        xs[c * 128 + l] = t;
    }
    __syncthreads();

    const int o0 = w * 8;
    unsigned long long A[4][4];
#pragma unroll
    for (int g = 0; g < 4; g++)
#pragma unroll
        for (int j = 0; j < 4; j++) A[g][j] = 0ull;

#pragma unroll 4
    for (int c = 0; c < 64; c++) {
        float4 xv = *reinterpret_cast<const float4*>(xs + c * 128 + lane * 4);
        const ulonglong2* wp = reinterpret_cast<const ulonglong2*>(ws + c * 128 + o0);
        ulonglong2 wA = wp[0], wB = wp[1];
        float xg[4] = {xv.x, xv.y, xv.z, xv.w};
#pragma unroll
        for (int g = 0; g < 4; g++) {
            unsigned long long x2 = pk2(xg[g], xg[g]);
            A[g][0] = f2fma(x2, wA.x, A[g][0]);
            A[g][1] = f2fma(x2, wA.y, A[g][1]);
            A[g][2] = f2fma(x2, wB.x, A[g][2]);
            A[g][3] = f2fma(x2, wB.y, A[g][3]);
        }
    }

    float h[4][8];
#pragma unroll
    for (int g = 0; g < 4; g++) {
        upk2(A[g][0], h[g][0], h[g][1]); upk2(A[g][1], h[g][2], h[g][3]);
        upk2(A[g][2], h[g][4], h[g][5]); upk2(A[g][3], h[g][6], h[g][7]);
    }
    const int base = bs0 * 32 + lane * 4;
#pragma unroll
    for (int j = 0; j < 8; j++) {
        float b4 = bias[o0 + j];
        float4 hv;
        hv.x = __fadd_rn(h[0][j], b4);
        hv.y = __fadd_rn(h[1][j], b4);
        hv.z = __fadd_rn(h[2][j], b4);
        hv.w = __fadd_rn(h[3][j], b4);
        *reinterpret_cast<float4*>(&g_h2[(o0 + j) * MM + base]) = hv;
        float sv = wredsum((hv.x + hv.y) + (hv.z + hv.w));
        float sq = wredsum((hv.x * hv.x + hv.y * hv.y) + (hv.z * hv.z + hv.w * hv.w));
        if (lane == 0) {
            g_ps2[(o0 + j) * NB2 + blockIdx.x] = sv;
            g_pq2[(o0 + j) * NB2 + blockIdx.x] = sq;
        }
    }
}

// extra-point mid layers (unchanged)
template <int COUT, int LAYER>
__global__ __launch_bounds__(COUT * 4) void gemm_midx_kernel(
    const float* __restrict__ W, const float* __restrict__ bias) {
    const float* hin = (LAYER == 1) ? g_e0 : g_e1;
    const float* ab  = (LAYER == 1) ? g_ab0 : g_ab1;
    float* hout = (LAYER == 1) ? g_e1 : g_e2;

    const int bs0 = blockIdx.x * 32;
    const int tid = threadIdx.x;
    const int lane = tid & 31;
    const int w = tid >> 5;
    const int NT = COUT * 4;

    __shared__ __align__(16) float ws[64 * COUT];
    __shared__ float xs[64 * 32];

    for (int i = tid; i < 64 * COUT; i += NT) {
        int o = i >> 6, c = i & 63;
        ws[c * COUT + o] = W[i];
    }
    for (int i = tid; i < 64 * 32; i += NT) {
        int c = i >> 5, l = i & 31;
        float v = hin[c * NG + bs0 + l];
        float t = __fmul_rn(__fmul_rn(__fsub_rn(v, ab[c]), ab[64 + c]), ab[128 + c]);
        t = fmaxf(__fadd_rn(t, ab[192 + c]), 0.0f);
        xs[i] = t;
    }
    __syncthreads();

    const int o0 = w * 8;
    unsigned long long a0 = 0ull, a1 = 0ull, a2 = 0ull, a3 = 0ull;
#pragma unroll 4
    for (int c = 0; c < 64; c++) {
        float xv = xs[c * 32 + lane];
        unsigned long long x2 = pk2(xv, xv);
        const ulonglong2* wp = reinterpret_cast<const ulonglong2*>(ws + c * COUT + o0);
        ulonglong2 wA = wp[0], wB = wp[1];
        a0 = f2fma(x2, wA.x, a0);
        a1 = f2fma(x2, wA.y, a1);
        a2 = f2fma(x2, wB.x, a2);
        a3 = f2fma(x2, wB.y, a3);
    }
    float h[8];
    upk2(a0, h[0], h[1]); upk2(a1, h[2], h[3]);
    upk2(a2, h[4], h[5]); upk2(a3, h[6], h[7]);
#pragma unroll
    for (int j = 0; j < 8; j++)
        hout[(o0 + j) * NG + bs0 + lane] = __fadd_rn(h[j], bias[o0 + j]);
}

// ------- 4. stats finalize from per-block partials (deterministic) -------
template <int L>
__global__ __launch_bounds__(256) void stats_fin_kernel(const float* __restrict__ gamma,
                                                        const float* __restrict__ beta) {
    const int C = (L == 2) ? 128 : 64;
    const int NBLK = (L == 0) ? NB0 : ((L == 1) ? NB1 : NB2);
    const float* ps = (L == 0) ? g_ps0 : ((L == 1) ? g_ps1 : g_ps2);
    const float* pq = (L == 0) ? g_pq0 : ((L == 1) ? g_pq1 : g_pq2);
    float* ab = (L == 0) ? g_ab0 : ((L == 1) ? g_ab1 : g_ab2);

    const int c = blockIdx.x;
    float s = 0.f, q = 0.f;
    for (int i = threadIdx.x; i < NBLK; i += 256) {
        s += ps[c * NBLK + i];
        q += pq[c * NBLK + i];
    }
    s = wredsum(s);
    q = wredsum(q);
    __shared__ float sh[16];
    int lane = threadIdx.x & 31, w = threadIdx.x >> 5;
    if (lane == 0) { sh[w] = s; sh[8 + w] = q; }
    __syncthreads();
    if (threadIdx.x == 0) {
        float ts = 0.f, tq = 0.f;
#pragma unroll
        for (int i = 0; i < 8; i++) { ts += sh[i]; tq += sh[8 + i]; }
        const float inv = 1.0f / (float)MM;
        float mu = ts * inv;
        float var = tq * inv - mu * mu;
        ab[c] = mu;
        ab[C + c] = 1.0f / sqrtf(var + 1e-5f);
        ab[2 * C + c] = gamma[c];
        ab[3 * C + c] = beta[c];
    }
}

// ---------------- 5. bn+relu + soft-blended max over K (FROZEN) ----------------
__global__ __launch_bounds__(128) void final_kernel(float* __restrict__ out) {
    const int bs = blockIdx.x;
    const int b = bs >> 10, s = bs & 1023;
    const int lane = threadIdx.x & 31, w = threadIdx.x >> 5;
    float* fo = out + BB * 3 * SS + b * 128 * SS + s;
    const int mbase = bs * 32 + lane;

    const int meta = g_umeta[bs];
    const int mode = meta & 3;
    const int disp = (meta >> 8) & 1;
    const int extraV = (meta >> 9) & 1;
    const int allExcl = (meta >> 10) & 1;
    const float wU = g_uw[bs];
    const int uIdx = g_uidx[bs];
    const int pidx = g_ball[bs * 32 + lane];

    for (int o = w; o < 128; o += 4) {
        float raw = g_h2[o * MM + mbase];
        float t = __fmul_rn(__fmul_rn(__fsub_rn(raw, g_ab2[o]), g_ab2[128 + o]),
                            g_ab2[256 + o]);
        float v = fmaxf(__fadd_rn(t, g_ab2[384 + o]), 0.0f);

        float res;
        if (mode == 0) {
            res = wredmax(v);
        } else {
            float eraw = g_e2[o * NG + bs];
            float et = __fmul_rn(__fmul_rn(__fsub_rn(eraw, g_ab2[o]), g_ab2[128 + o]),
                                 g_ab2[256 + o]);
            float ve = fmaxf(__fadd_rn(et, g_ab2[384 + o]), 0.0f);
            float A, B;
            if (mode == 1) {
                A = wredmax(v);
                float vB = (pidx == uIdx) ? -1e30f : v;
                B = wredmax(vB);
                if (extraV) B = fmaxf(B, ve);
            } else {
                float vA = ((disp && lane == 31) || allExcl) ? -1e30f : v;
                A = fmaxf(wredmax(vA), ve);
                B = wredmax(v);
            }
            res = wU * A + (1.0f - wU) * B;
        }
        if (lane == 0) fo[o * SS] = res;
    }
}

// ---------------- launcher ----------------
extern "C" void kernel_launch(void* const* d_in, const int* in_sizes, int n_in,
                              void* d_out, int out_size) {
    const float* pc   = (const float*)d_in[0];
    const float* feat = (const float*)d_in[1];
    const float* W0 = (const float*)d_in[2];
    const float* b0 = (const float*)d_in[3];
    const float* g0 = (const float*)d_in[4];
    const float* e0 = (const float*)d_in[5];
    const float* W1 = (const float*)d_in[6];
    const float* b1 = (const float*)d_in[7];
    const float* g1 = (const float*)d_in[8];
    const float* e1 = (const float*)d_in[9];
    const float* W2 = (const float*)d_in[10];
    const float* b2 = (const float*)d_in[11];
    const float* g2 = (const float*)d_in[12];
    const float* e2 = (const float*)d_in[13];
    float* out = (float*)d_out;

    const int SM0 = (67 * 64 + 67 * 128) * 4;     // 52,416 B
    const int SM2 = (64 * 128 + 64 * 128) * 4;    // 65,536 B
    static int attr_done = 0;
    if (!attr_done) {
        cudaFuncSetAttribute(gemm0_kernel,
                             cudaFuncAttributeMaxDynamicSharedMemorySize, SM0);
        cudaFuncSetAttribute(gemm_mid2_kernel,
                             cudaFuncAttributeMaxDynamicSharedMemorySize, SM2);
        attr_done = 1;
    }

    fps_kernel<<<BB, 1024>>>(pc, out);
    ball_kernel<<<NG / 8, 256>>>(pc);
    gemm0x_kernel<<<NG / 32, 256>>>(pc, feat, W0, b0);
    gemm0_kernel<<<NB0, 256, SM0>>>(pc, feat, W0, b0);
    stats_fin_kernel<0><<<64, 256>>>(g0, e0);
    gemm_mid1_kernel<<<NB1, 256>>>(W1, b1);
    gemm_midx_kernel<64, 1><<<NG / 32, 256>>>(W1, b1);
    stats_fin_kernel<1><<<64, 256>>>(g1, e1);
    gemm_mid2_kernel<<<NB2, 512, SM2>>>(W2, b2);
    gemm_midx_kernel<128, 2><<<NG / 32, 512>>>(W2, b2);
    stats_fin_kernel<2><<<128, 256>>>(g2, e2);
    final_kernel<<<NG, 128>>>(out);
}

// round 17
// speedup vs baseline: 1.5430x; 1.0375x over previous
#include <cuda_runtime.h>

#define BB 16
#define NN 4096
#define SS 1024
#define KS 32
#define NG (BB*SS)            /* 16384 groups */
#define MM (NG*KS)            /* 524288 samples */
#define NB0 (NG/8)            /* 2048 */
#define NB1 (NG/8)            /* 2048 */
#define NB2 (NG/4)            /* 4096 */

// ---------------- scratch (device globals; no allocation) ----------------
__device__ float g_new_xyz[NG*3];
__device__ int   g_ball[NG*KS];
__device__ float g_h0[64*MM];
__device__ float g_h1[64*MM];
__device__ float g_h2[128*MM];
__device__ float g_e0[64*NG];
__device__ float g_e1[64*NG];
__device__ float g_e2[128*NG];
__device__ int   g_extra[NG];
__device__ int   g_uidx[NG];
__device__ int   g_umeta[NG];
__device__ float g_uw[NG];
__device__ float g_ab0[256];
__device__ float g_ab1[256];
__device__ float g_ab2[512];
__device__ float g_ps0[64*NB0],  g_pq0[64*NB0];
__device__ float g_ps1[64*NB1],  g_pq1[64*NB1];
__device__ float g_ps2[128*NB2], g_pq2[128*NB2];

// ---------------- helpers ----------------
__device__ __forceinline__ unsigned long long pk2(float a, float b) {
    unsigned long long r;
    asm("mov.b64 %0, {%1,%2};" : "=l"(r) : "f"(a), "f"(b));
    return r;
}
__device__ __forceinline__ void upk2(unsigned long long v, float& a, float& b) {
    asm("mov.b64 {%0,%1}, %2;" : "=f"(a), "=f"(b) : "l"(v));
}
__device__ __forceinline__ unsigned long long f2fma(unsigned long long a,
                                                    unsigned long long b,
                                                    unsigned long long c) {
    unsigned long long d;
    asm("fma.rn.f32x2 %0, %1, %2, %3;" : "=l"(d) : "l"(a), "l"(b), "l"(c));
    return d;
}
__device__ __forceinline__ float wredsum(float v) {
#pragma unroll
    for (int o = 16; o > 0; o >>= 1) v += __shfl_xor_sync(0xFFFFFFFFu, v, o);
    return v;
}
__device__ __forceinline__ float hredsum16(float v) {
#pragma unroll
    for (int o = 8; o > 0; o >>= 1) v += __shfl_xor_sync(0xFFFFFFFFu, v, o);
    return v;
}
__device__ __forceinline__ float wredmax(float v) {
#pragma unroll
    for (int o = 16; o > 0; o >>= 1) v = fmaxf(v, __shfl_xor_sync(0xFFFFFFFFu, v, o));
    return v;
}

// ---------------- 1. farthest point sampling (bit-exact, FROZEN) ----------------
__global__ __launch_bounds__(1024) void fps_kernel(const float* __restrict__ pc,
                                                   float* __restrict__ out) {
    const int b = blockIdx.x;
    const int tid = threadIdx.x;
    const float* px = pc + b * 3 * NN;
    const float* py = px + NN;
    const float* pz = px + 2 * NN;

    float lx[4], ly[4], lz[4], ld[4];
#pragma unroll
    for (int j = 0; j < 4; j++) {
        int p = tid + j * 1024;
        lx[j] = px[p]; ly[j] = py[p]; lz[j] = pz[p];
        ld[j] = 1e10f;
    }
    __shared__ unsigned long long swk[32];
    __shared__ int sfar;

    int far = 0;
    for (int s = 0; s < SS; s++) {
        float cx = __ldg(px + far), cy = __ldg(py + far), cz = __ldg(pz + far);
        if (tid == 0) {
            out[b * 3 * SS + s]          = cx;
            out[b * 3 * SS + SS + s]     = cy;
            out[b * 3 * SS + 2 * SS + s] = cz;
            int bs = b * SS + s;
            g_new_xyz[bs * 3 + 0] = cx;
            g_new_xyz[bs * 3 + 1] = cy;
            g_new_xyz[bs * 3 + 2] = cz;
        }
        float ncx = -cx, ncy = -cy, ncz = -cz;
        float bd = 0.0f;
        int bi = tid;
#pragma unroll
        for (int j = 0; j < 4; j++) {
            float dx = __fadd_rn(lx[j], ncx);
            float dy = __fadd_rn(ly[j], ncy);
            float dz = __fadd_rn(lz[j], ncz);
            float d = __fadd_rn(__fadd_rn(__fmul_rn(dx, dx), __fmul_rn(dy, dy)),
                                __fmul_rn(dz, dz));
            float nd = fminf(ld[j], d);
            ld[j] = nd;
            if (nd > bd) { bd = nd; bi = tid + j * 1024; }
        }
        unsigned long long key =
            ((unsigned long long)__float_as_uint(bd) << 32) |
            (unsigned long long)(0xFFFFFFFFu - (unsigned)bi);
#pragma unroll
        for (int off = 16; off > 0; off >>= 1) {
            unsigned long long o = __shfl_down_sync(0xFFFFFFFFu, key, off);
            if (o > key) key = o;
        }
        if ((tid & 31) == 0) swk[tid >> 5] = key;
        __syncthreads();
        if (tid < 32) {
            unsigned long long k = swk[tid];
#pragma unroll
            for (int off = 16; off > 0; off >>= 1) {
                unsigned long long o = __shfl_down_sync(0xFFFFFFFFu, k, off);
                if (o > k) k = o;
            }
            if (tid == 0)
                sfar = (int)(0xFFFFFFFFu - (unsigned)(k & 0xFFFFFFFFull));
        }
        __syncthreads();
        far = sfar;
    }
}

// ------- 2. ball query with borderline-uncertainty tracking (FROZEN) -------
__global__ __launch_bounds__(256) void ball_kernel(const float* __restrict__ pc) {
    const int gw = (blockIdx.x * 256 + threadIdx.x) >> 5;
    const int lane = threadIdx.x & 31;
    const int wslot = (threadIdx.x >> 5);
    const int b = gw >> 10;
    const float* px = pc + b * 3 * NN;
    const float* py = px + NN;
    const float* pz = px + 2 * NN;

    float sx = g_new_xyz[gw * 3 + 0];
    float sy = g_new_xyz[gw * 3 + 1];
    float sz = g_new_xyz[gw * 3 + 2];
    float ss = __fadd_rn(__fadd_rn(__fmul_rn(sx, sx), __fmul_rn(sy, sy)),
                         __fmul_rn(sz, sz));
    const float R2 = (float)(0.2 * 0.2);
    const double R2D = (double)R2;
    const double sxd = (double)sx, syd = (double)sy, szd = (double)sz;

    __shared__ int sidx[8][32];
    __shared__ int salt[8];
    int* my = sidx[wslot];
    if (lane == 0) salt[wslot] = -1;
    __syncwarp();

    float aD = 1e30f;
    float aSD = 0.f;
    int aI = -1, aP = 0;

    int cnt = 0;
    for (int base = 0; base < NN; base += 32) {
        int i = base + lane;
        float x = px[i], y = py[i], z = pz[i];
        float pp = __fadd_rn(__fadd_rn(__fmul_rn(x, x), __fmul_rn(y, y)),
                             __fmul_rn(z, z));
        float dot = __fmaf_rn(sz, z, __fmaf_rn(sy, y, __fmul_rn(sx, x)));
        float d = __fadd_rn(__fadd_rn(__fmul_rn(-2.0f, dot), ss), pp);
        bool isLast = (i == NN - 1);
        bool valid;
        if (fabsf(d - R2) < 1e-4f) {
            double dx = sxd - (double)x;
            double dy = syd - (double)y;
            double dz = szd - (double)z;
            double dd = dx * dx + dy * dy + dz * dz;
            valid = (dd <= R2D);
            if (!isLast) {
                float sd = (float)(R2D - dd);
                float ad = fabsf(sd);
                if (ad < 1.2e-6f && ad < aD) {
                    aD = ad; aSD = sd; aI = i; aP = valid ? 1 : 0;
                }
            }
        } else {
            valid = !(d > R2);
        }
        valid = valid && !isLast;
        unsigned m = __ballot_sync(0xFFFFFFFFu, valid);
        int pos = cnt + __popc(m & ((1u << lane) - 1u));
        if (valid && pos < KS) my[pos] = i;
        if (valid && pos == KS) salt[wslot] = i;
        cnt += __popc(m);
        if (cnt >= KS + 1) break;
    }
    __syncwarp();

#pragma unroll
    for (int off = 16; off > 0; off >>= 1) {
        float oD = __shfl_xor_sync(0xFFFFFFFFu, aD, off);
        float oSD = __shfl_xor_sync(0xFFFFFFFFu, aSD, off);
        int oI = __shfl_xor_sync(0xFFFFFFFFu, aI, off);
        int oP = __shfl_xor_sync(0xFFFFFFFFu, aP, off);
        if (oD < aD || (oD == aD && oI >= 0 && (aI < 0 || oI < aI))) {
            aD = oD; aSD = oSD; aI = oI; aP = oP;
        }
    }

    int c2 = cnt < KS ? cnt : KS;
    int vball;
    if (cnt == 0) vball = NN - 1;
    else vball = (lane < c2) ? my[lane] : my[0];
    g_ball[gw * KS + lane] = vball;

    int mode = 0, us = 0, disp = 0, allExcl = 0, extraIdx = -1;
    float w = 0.5f;
    if (aI >= 0 && aD < 1.2e-6f) {
        w = fminf(fmaxf(0.5f + aSD * (1.0f / 8e-7f), 0.0f), 1.0f);
        if (aP) {
            bool mine = (lane < c2) && (my[lane] == aI);
            unsigned mm = __ballot_sync(0xFFFFFFFFu, mine);
            if (mm) {
                mode = 1;
                us = __ffs(mm) - 1;
                if (cnt == 1) extraIdx = NN - 1;
                else extraIdx = salt[wslot];
            }
        } else {
            bool relevant = (cnt < KS) || (aI < my[KS - 1]);
            if (relevant) {
                mode = 2;
                disp = (cnt >= KS) ? 1 : 0;
                allExcl = (cnt == 0) ? 1 : 0;
                extraIdx = aI;
            }
        }
    }
    if (lane == 0) {
        g_umeta[gw] = mode | (us << 2) | (disp << 8) |
                      ((extraIdx >= 0 ? 1 : 0) << 9) | (allExcl << 10);
        g_uw[gw] = w;
        g_uidx[gw] = aI;
        g_extra[gw] = (extraIdx >= 0) ? extraIdx : (NN - 1);
    }
}

// ---------------- 3x. layer-0 for extra points (FROZEN) ----------------
__global__ __launch_bounds__(256) void gemm0x_kernel(const float* __restrict__ pc,
                                                     const float* __restrict__ feat,
                                                     const float* __restrict__ W,
                                                     const float* __restrict__ bias) {
    const int bs0 = blockIdx.x * 32;
    const int b = bs0 >> 10;
    const int tid = threadIdx.x;
    const int lane = tid & 31;
    const int w = tid >> 5;

    __shared__ __align__(16) float ws[67 * 64];
    __shared__ float xs[67 * 32];
    __shared__ int sidx[32];

    for (int i = tid; i < 67 * 64; i += 256) {
        int o = i / 67, c = i - o * 67;
        ws[c * 64 + o] = W[i];
    }
    if (tid < 32) sidx[tid] = g_extra[bs0 + tid];
    __syncthreads();

    const float* pb = pc + b * 3 * NN;
    const float* fb = feat + b * 64 * NN;
    for (int i = tid; i < 67 * 32; i += 256) {
        int c = i >> 5, l = i & 31;
        int p = sidx[l];
        float v;
        if (c < 3) v = __fsub_rn(pb[c * NN + p], g_new_xyz[(bs0 + l) * 3 + c]);
        else       v = fb[(c - 3) * NN + p];
        xs[i] = v;
    }
    __syncthreads();

    const int o0 = w * 8;
    unsigned long long a0 = 0ull, a1 = 0ull, a2 = 0ull, a3 = 0ull;
#pragma unroll 4
    for (int c = 0; c < 67; c++) {
        float xv = xs[c * 32 + lane];
        unsigned long long x2 = pk2(xv, xv);
        const ulonglong2* wp = reinterpret_cast<const ulonglong2*>(ws + c * 64 + o0);
        ulonglong2 wA = wp[0], wB = wp[1];
        a0 = f2fma(x2, wA.x, a0);
        a1 = f2fma(x2, wA.y, a1);
        a2 = f2fma(x2, wB.x, a2);
        a3 = f2fma(x2, wB.y, a3);
    }
    float h[8];
    upk2(a0, h[0], h[1]); upk2(a1, h[2], h[3]);
    upk2(a2, h[4], h[5]); upk2(a3, h[6], h[7]);
#pragma unroll
    for (int j = 0; j < 8; j++)
        g_e0[(o0 + j) * NG + bs0 + lane] = __fadd_rn(h[j], bias[o0 + j]);
}

// ------- 3. layer-0 GEMM: 8 groups/block, 8x8 register tile -------
__global__ __launch_bounds__(256) void gemm0_kernel(const float* __restrict__ pc,
                                                    const float* __restrict__ feat,
                                                    const float* __restrict__ W,
                                                    const float* __restrict__ bias) {
    extern __shared__ __align__(16) float smem0[];
    float* ws = smem0;                 // 67*64
    float* xs = smem0 + 67 * 64;       // 67*256
    __shared__ int sidx[256];

    const int bs0 = blockIdx.x * 8;
    const int b = bs0 >> 10;
    const int tid = threadIdx.x;
    const int col = tid >> 5;          // 0..7  (output block, = warp id)
    const int row = tid & 31;          // 0..31 (sample block of 8)

    for (int i = tid; i < 67 * 64; i += 256) {
        int o = i / 67, c = i - o * 67;
        ws[c * 64 + o] = W[i];
    }
    sidx[tid] = g_ball[bs0 * 32 + tid];
    __syncthreads();

    const float* pb = pc + b * 3 * NN;
    const float* fb = feat + b * 64 * NN;
    for (int i = tid; i < 67 * 256; i += 256) {
        int c = i >> 8, s = i & 255;
        int p = sidx[s];
        float v;
        if (c < 3) v = __fsub_rn(pb[c * NN + p], g_new_xyz[(bs0 + (s >> 5)) * 3 + c]);
        else       v = fb[(c - 3) * NN + p];
        xs[c * 256 + s] = v;
    }
    __syncthreads();

    const int o0 = col * 8;
    unsigned long long A[8][4];
#pragma unroll
    for (int s = 0; s < 8; s++)
#pragma unroll
        for (int j = 0; j < 4; j++) A[s][j] = 0ull;

#pragma unroll 2
    for (int c = 0; c < 67; c++) {
        float4 xa = *reinterpret_cast<const float4*>(xs + c * 256 + row * 8);
        float4 xb = *reinterpret_cast<const float4*>(xs + c * 256 + row * 8 + 4);
        const ulonglong2* wp = reinterpret_cast<const ulonglong2*>(ws + c * 64 + o0);
        ulonglong2 w0 = wp[0], w1 = wp[1];
        float xg[8] = {xa.x, xa.y, xa.z, xa.w, xb.x, xb.y, xb.z, xb.w};
#pragma unroll
        for (int s = 0; s < 8; s++) {
            unsigned long long x2 = pk2(xg[s], xg[s]);
            A[s][0] = f2fma(x2, w0.x, A[s][0]);
            A[s][1] = f2fma(x2, w0.y, A[s][1]);
            A[s][2] = f2fma(x2, w1.x, A[s][2]);
            A[s][3] = f2fma(x2, w1.y, A[s][3]);
        }
    }

    float h[8][8];   // [sample][output]
#pragma unroll
    for (int s = 0; s < 8; s++) {
        upk2(A[s][0], h[s][0], h[s][1]); upk2(A[s][1], h[s][2], h[s][3]);
        upk2(A[s][2], h[s][4], h[s][5]); upk2(A[s][3], h[s][6], h[s][7]);
    }
    const int sbase = bs0 * 32 + row * 8;
#pragma unroll
    for (int j = 0; j < 8; j++) {
        float b4 = bias[o0 + j];
        float4 v0, v1;
        v0.x = __fadd_rn(h[0][j], b4); v0.y = __fadd_rn(h[1][j], b4);
        v0.z = __fadd_rn(h[2][j], b4); v0.w = __fadd_rn(h[3][j], b4);
        v1.x = __fadd_rn(h[4][j], b4); v1.y = __fadd_rn(h[5][j], b4);
        v1.z = __fadd_rn(h[6][j], b4); v1.w = __fadd_rn(h[7][j], b4);
        *reinterpret_cast<float4*>(&g_h0[(o0 + j) * MM + sbase]) = v0;
        *reinterpret_cast<float4*>(&g_h0[(o0 + j) * MM + sbase + 4]) = v1;
        float sloc = ((v0.x + v0.y) + (v0.z + v0.w)) + ((v1.x + v1.y) + (v1.z + v1.w));
        float qloc = ((v0.x*v0.x + v0.y*v0.y) + (v0.z*v0.z + v0.w*v0.w)) +
                     ((v1.x*v1.x + v1.y*v1.y) + (v1.z*v1.z + v1.w*v1.w));
        sloc = wredsum(sloc);
        qloc = wredsum(qloc);
        if (row == 0) {
            g_ps0[(o0 + j) * NB0 + blockIdx.x] = sloc;
            g_pq0[(o0 + j) * NB0 + blockIdx.x] = qloc;
        }
    }
}

// ------- 3b. mid layer1: 8 groups/block, 8x8 register tile -------
__global__ __launch_bounds__(256) void gemm_mid1_kernel(const float* __restrict__ W,
                                                        const float* __restrict__ bias) {
    extern __shared__ __align__(16) float smem1[];
    float* ws = smem1;                 // 64*64
    float* xs = smem1 + 64 * 64;       // 64*256

    const int bs0 = blockIdx.x * 8;
    const int tid = threadIdx.x;
    const int col = tid >> 5;
    const int row = tid & 31;

    for (int i = tid; i < 64 * 64; i += 256) {
        int o = i >> 6, c = i & 63;
        ws[c * 64 + o] = W[i];
    }
    const float* ab = g_ab0;
    for (int i = tid; i < 64 * 256; i += 256) {
        int c = i >> 8, l = i & 255;
        float v = g_h0[c * MM + bs0 * 32 + l];
        float t = __fmul_rn(__fmul_rn(__fsub_rn(v, ab[c]), ab[64 + c]), ab[128 + c]);
        t = fmaxf(__fadd_rn(t, ab[192 + c]), 0.0f);
        xs[c * 256 + l] = t;
    }
    __syncthreads();

    const int o0 = col * 8;
    unsigned long long A[8][4];
#pragma unroll
    for (int s = 0; s < 8; s++)
#pragma unroll
        for (int j = 0; j < 4; j++) A[s][j] = 0ull;

#pragma unroll 2
    for (int c = 0; c < 64; c++) {
        float4 xa = *reinterpret_cast<const float4*>(xs + c * 256 + row * 8);
        float4 xb = *reinterpret_cast<const float4*>(xs + c * 256 + row * 8 + 4);
        const ulonglong2* wp = reinterpret_cast<const ulonglong2*>(ws + c * 64 + o0);
        ulonglong2 w0 = wp[0], w1 = wp[1];
        float xg[8] = {xa.x, xa.y, xa.z, xa.w, xb.x, xb.y, xb.z, xb.w};
#pragma unroll
        for (int s = 0; s < 8; s++) {
            unsigned long long x2 = pk2(xg[s], xg[s]);
            A[s][0] = f2fma(x2, w0.x, A[s][0]);
            A[s][1] = f2fma(x2, w0.y, A[s][1]);
            A[s][2] = f2fma(x2, w1.x, A[s][2]);
            A[s][3] = f2fma(x2, w1.y, A[s][3]);
        }
    }

    float h[8][8];
#pragma unroll
    for (int s = 0; s < 8; s++) {
        upk2(A[s][0], h[s][0], h[s][1]); upk2(A[s][1], h[s][2], h[s][3]);
        upk2(A[s][2], h[s][4], h[s][5]); upk2(A[s][3], h[s][6], h[s][7]);
    }
    const int sbase = bs0 * 32 + row * 8;
#pragma unroll
    for (int j = 0; j < 8; j++) {
        float b4 = bias[o0 + j];
        float4 v0, v1;
        v0.x = __fadd_rn(h[0][j], b4); v0.y = __fadd_rn(h[1][j], b4);
        v0.z = __fadd_rn(h[2][j], b4); v0.w = __fadd_rn(h[3][j], b4);
        v1.x = __fadd_rn(h[4][j], b4); v1.y = __fadd_rn(h[5][j], b4);
        v1.z = __fadd_rn(h[6][j], b4); v1.w = __fadd_rn(h[7][j], b4);
        *reinterpret_cast<float4*>(&g_h1[(o0 + j) * MM + sbase]) = v0;
        *reinterpret_cast<float4*>(&g_h1[(o0 + j) * MM + sbase + 4]) = v1;
        float sloc = ((v0.x + v0.y) + (v0.z + v0.w)) + ((v1.x + v1.y) + (v1.z + v1.w));
        float qloc = ((v0.x*v0.x + v0.y*v0.y) + (v0.z*v0.z + v0.w*v0.w)) +
                     ((v1.x*v1.x + v1.y*v1.y) + (v1.z*v1.z + v1.w*v1.w));
        sloc = wredsum(sloc);
        qloc = wredsum(qloc);
        if (row == 0) {
            g_ps1[(o0 + j) * NB1 + blockIdx.x] = sloc;
            g_pq1[(o0 + j) * NB1 + blockIdx.x] = qloc;
        }
    }
}

// ------- 3c. mid layer2: 4 groups/block, 8x8 tile, 16x16 thread grid -------
__global__ __launch_bounds__(256) void gemm_mid2_kernel(const float* __restrict__ W,
                                                        const float* __restrict__ bias) {
    extern __shared__ __align__(16) float smem2[];
    float* ws = smem2;                 // 64*128
    float* xs = smem2 + 64 * 128;      // 64*128

    const int bs0 = blockIdx.x * 4;
    const int tid = threadIdx.x;
    const int col = tid >> 4;          // 0..15 (output block)
    const int row = tid & 15;          // 0..15 (sample block of 8)

    for (int i = tid; i < 64 * 128; i += 256) {
        int o = i >> 6, c = i & 63;
        ws[c * 128 + o] = W[i];
    }
    const float* ab = g_ab1;
    for (int i = tid; i < 64 * 128; i += 256) {
        int c = i >> 7, l = i & 127;
        float v = g_h1[c * MM + bs0 * 32 + l];
        float t = __fmul_rn(__fmul_rn(__fsub_rn(v, ab[c]), ab[64 + c]), ab[128 + c]);
        t = fmaxf(__fadd_rn(t, ab[192 + c]), 0.0f);
        xs[c * 128 + l] = t;
    }
    __syncthreads();

    const int o0 = col * 8;
    unsigned long long A[8][4];
#pragma unroll
    for (int s = 0; s < 8; s++)
#pragma unroll
        for (int j = 0; j < 4; j++) A[s][j] = 0ull;

#pragma unroll 2
    for (int c = 0; c < 64; c++) {
        float4 xa = *reinterpret_cast<const float4*>(xs + c * 128 + row * 8);
        float4 xb = *reinterpret_cast<const float4*>(xs + c * 128 + row * 8 + 4);
        const ulonglong2* wp = reinterpret_cast<const ulonglong2*>(ws + c * 128 + o0);
        ulonglong2 w0 = wp[0], w1 = wp[1];
        float xg[8] = {xa.x, xa.y, xa.z, xa.w, xb.x, xb.y, xb.z, xb.w};
#pragma unroll
        for (int s = 0; s < 8; s++) {
            unsigned long long x2 = pk2(xg[s], xg[s]);
            A[s][0] = f2fma(x2, w0.x, A[s][0]);
            A[s][1] = f2fma(x2, w0.y, A[s][1]);
            A[s][2] = f2fma(x2, w1.x, A[s][2]);
            A[s][3] = f2fma(x2, w1.y, A[s][3]);
        }
    }

    float h[8][8];
#pragma unroll
    for (int s = 0; s < 8; s++) {
        upk2(A[s][0], h[s][0], h[s][1]); upk2(A[s][1], h[s][2], h[s][3]);
        upk2(A[s][2], h[s][4], h[s][5]); upk2(A[s][3], h[s][6], h[s][7]);
    }
    const int sbase = bs0 * 32 + row * 8;
#pragma unroll
    for (int j = 0; j < 8; j++) {
        float b4 = bias[o0 + j];
        float4 v0, v1;
        v0.x = __fadd_rn(h[0][j], b4); v0.y = __fadd_rn(h[1][j], b4);
        v0.z = __fadd_rn(h[2][j], b4); v0.w = __fadd_rn(h[3][j], b4);
        v1.x = __fadd_rn(h[4][j], b4); v1.y = __fadd_rn(h[5][j], b4);
        v1.z = __fadd_rn(h[6][j], b4); v1.w = __fadd_rn(h[7][j], b4);
        *reinterpret_cast<float4*>(&g_h2[(o0 + j) * MM + sbase]) = v0;
        *reinterpret_cast<float4*>(&g_h2[(o0 + j) * MM + sbase + 4]) = v1;
        float sloc = ((v0.x + v0.y) + (v0.z + v0.w)) + ((v1.x + v1.y) + (v1.z + v1.w));
        float qloc = ((v0.x*v0.x + v0.y*v0.y) + (v0.z*v0.z + v0.w*v0.w)) +
                     ((v1.x*v1.x + v1.y*v1.y) + (v1.z*v1.z + v1.w*v1.w));
        sloc = hredsum16(sloc);
        qloc = hredsum16(qloc);
        if (row == 0) {
            g_ps2[(o0 + j) * NB2 + blockIdx.x] = sloc;
            g_pq2[(o0 + j) * NB2 + blockIdx.x] = qloc;
        }
    }
}

// extra-point mid layers (FROZEN)
template <int COUT, int LAYER>
__global__ __launch_bounds__(COUT * 4) void gemm_midx_kernel(
    const float* __restrict__ W, const float* __restrict__ bias) {
    const float* hin = (LAYER == 1) ? g_e0 : g_e1;
    const float* ab  = (LAYER == 1) ? g_ab0 : g_ab1;
    float* hout = (LAYER == 1) ? g_e1 : g_e2;

    const int bs0 = blockIdx.x * 32;
    const int tid = threadIdx.x;
    const int lane = tid & 31;
    const int w = tid >> 5;
    const int NT = COUT * 4;

    __shared__ __align__(16) float ws[64 * COUT];
    __shared__ float xs[64 * 32];

    for (int i = tid; i < 64 * COUT; i += NT) {
        int o = i >> 6, c = i & 63;
        ws[c * COUT + o] = W[i];
    }
    for (int i = tid; i < 64 * 32; i += NT) {
        int c = i >> 5, l = i & 31;
        float v = hin[c * NG + bs0 + l];
        float t = __fmul_rn(__fmul_rn(__fsub_rn(v, ab[c]), ab[64 + c]), ab[128 + c]);
        t = fmaxf(__fadd_rn(t, ab[192 + c]), 0.0f);
        xs[i] = t;
    }
    __syncthreads();

    const int o0 = w * 8;
    unsigned long long a0 = 0ull, a1 = 0ull, a2 = 0ull, a3 = 0ull;
#pragma unroll 4
    for (int c = 0; c < 64; c++) {
        float xv = xs[c * 32 + lane];
        unsigned long long x2 = pk2(xv, xv);
        const ulonglong2* wp = reinterpret_cast<const ulonglong2*>(ws + c * COUT + o0);
        ulonglong2 wA = wp[0], wB = wp[1];
        a0 = f2fma(x2, wA.x, a0);
        a1 = f2fma(x2, wA.y, a1);
        a2 = f2fma(x2, wB.x, a2);
        a3 = f2fma(x2, wB.y, a3);
    }
    float h[8];
    upk2(a0, h[0], h[1]); upk2(a1, h[2], h[3]);
    upk2(a2, h[4], h[5]); upk2(a3, h[6], h[7]);
#pragma unroll
    for (int j = 0; j < 8; j++)
        hout[(o0 + j) * NG + bs0 + lane] = __fadd_rn(h[j], bias[o0 + j]);
}

// ------- 4. stats finalize from per-block partials (deterministic) -------
template <int L>
__global__ __launch_bounds__(256) void stats_fin_kernel(const float* __restrict__ gamma,
                                                        const float* __restrict__ beta) {
    const int C = (L == 2) ? 128 : 64;
    const int NBLK = (L == 0) ? NB0 : ((L == 1) ? NB1 : NB2);
    const float* ps = (L == 0) ? g_ps0 : ((L == 1) ? g_ps1 : g_ps2);
    const float* pq = (L == 0) ? g_pq0 : ((L == 1) ? g_pq1 : g_pq2);
    float* ab = (L == 0) ? g_ab0 : ((L == 1) ? g_ab1 : g_ab2);

    const int c = blockIdx.x;
    float s = 0.f, q = 0.f;
    for (int i = threadIdx.x; i < NBLK; i += 256) {
        s += ps[c * NBLK + i];
        q += pq[c * NBLK + i];
    }
    s = wredsum(s);
    q = wredsum(q);
    __shared__ float sh[16];
    int lane = threadIdx.x & 31, w = threadIdx.x >> 5;
    if (lane == 0) { sh[w] = s; sh[8 + w] = q; }
    __syncthreads();
    if (threadIdx.x == 0) {
        float ts = 0.f, tq = 0.f;
#pragma unroll
        for (int i = 0; i < 8; i++) { ts += sh[i]; tq += sh[8 + i]; }
        const float inv = 1.0f / (float)MM;
        float mu = ts * inv;
        float var = tq * inv - mu * mu;
        ab[c] = mu;
        ab[C + c] = 1.0f / sqrtf(var + 1e-5f);
        ab[2 * C + c] = gamma[c];
        ab[3 * C + c] = beta[c];
    }
}

// ---------------- 5. bn+relu + soft-blended max over K (FROZEN) ----------------
__global__ __launch_bounds__(128) void final_kernel(float* __restrict__ out) {
    const int bs = blockIdx.x;
    const int b = bs >> 10, s = bs & 1023;
    const int lane = threadIdx.x & 31, w = threadIdx.x >> 5;
    float* fo = out + BB * 3 * SS + b * 128 * SS + s;
    const int mbase = bs * 32 + lane;

    const int meta = g_umeta[bs];
    const int mode = meta & 3;
    const int disp = (meta >> 8) & 1;
    const int extraV = (meta >> 9) & 1;
    const int allExcl = (meta >> 10) & 1;
    const float wU = g_uw[bs];
    const int uIdx = g_uidx[bs];
    const int pidx = g_ball[bs * 32 + lane];

    for (int o = w; o < 128; o += 4) {
        float raw = g_h2[o * MM + mbase];
        float t = __fmul_rn(__fmul_rn(__fsub_rn(raw, g_ab2[o]), g_ab2[128 + o]),
                            g_ab2[256 + o]);
        float v = fmaxf(__fadd_rn(t, g_ab2[384 + o]), 0.0f);

        float res;
        if (mode == 0) {
            res = wredmax(v);
        } else {
            float eraw = g_e2[o * NG + bs];
            float et = __fmul_rn(__fmul_rn(__fsub_rn(eraw, g_ab2[o]), g_ab2[128 + o]),
                                 g_ab2[256 + o]);
            float ve = fmaxf(__fadd_rn(et, g_ab2[384 + o]), 0.0f);
            float A, B;
            if (mode == 1) {
                A = wredmax(v);
                float vB = (pidx == uIdx) ? -1e30f : v;
                B = wredmax(vB);
                if (extraV) B = fmaxf(B, ve);
            } else {
                float vA = ((disp && lane == 31) || allExcl) ? -1e30f : v;
                A = fmaxf(wredmax(vA), ve);
                B = wredmax(v);
            }
            res = wU * A + (1.0f - wU) * B;
        }
        if (lane == 0) fo[o * SS] = res;
    }
}

// ---------------- launcher ----------------
extern "C" void kernel_launch(void* const* d_in, const int* in_sizes, int n_in,
                              void* d_out, int out_size) {
    const float* pc   = (const float*)d_in[0];
    const float* feat = (const float*)d_in[1];
    const float* W0 = (const float*)d_in[2];
    const float* b0 = (const float*)d_in[3];
    const float* g0 = (const float*)d_in[4];
    const float* e0 = (const float*)d_in[5];
    const float* W1 = (const float*)d_in[6];
    const float* b1 = (const float*)d_in[7];
    const float* g1 = (const float*)d_in[8];
    const float* e1 = (const float*)d_in[9];
    const float* W2 = (const float*)d_in[10];
    const float* b2 = (const float*)d_in[11];
    const float* g2 = (const float*)d_in[12];
    const float* e2 = (const float*)d_in[13];
    float* out = (float*)d_out;

    const int SM0 = (67 * 64 + 67 * 256) * 4;     // 85,760 B
    const int SM1 = (64 * 64 + 64 * 256) * 4;     // 81,920 B
    const int SM2 = (64 * 128 + 64 * 128) * 4;    // 65,536 B
    static int attr_done = 0;
    if (!attr_done) {
        cudaFuncSetAttribute(gemm0_kernel,
                             cudaFuncAttributeMaxDynamicSharedMemorySize, SM0);
        cudaFuncSetAttribute(gemm_mid1_kernel,
                             cudaFuncAttributeMaxDynamicSharedMemorySize, SM1);
        cudaFuncSetAttribute(gemm_mid2_kernel,
                             cudaFuncAttributeMaxDynamicSharedMemorySize, SM2);
        attr_done = 1;
    }

    fps_kernel<<<BB, 1024>>>(pc, out);
    ball_kernel<<<NG / 8, 256>>>(pc);
    gemm0x_kernel<<<NG / 32, 256>>>(pc, feat, W0, b0);
    gemm0_kernel<<<NB0, 256, SM0>>>(pc, feat, W0, b0);
    stats_fin_kernel<0><<<64, 256>>>(g0, e0);
    gemm_mid1_kernel<<<NB1, 256, SM1>>>(W1, b1);
    gemm_midx_kernel<64, 1><<<NG / 32, 256>>>(W1, b1);
    stats_fin_kernel<1><<<64, 256>>>(g1, e1);
    gemm_mid2_kernel<<<NB2, 256, SM2>>>(W2, b2);
    gemm_midx_kernel<128, 2><<<NG / 32, 512>>>(W2, b2);
    stats_fin_kernel<2><<<128, 256>>>(g2, e2);
    final_kernel<<<NG, 128>>>(out);
}